// round 2
// baseline (speedup 1.0000x reference)
#include <cuda_runtime.h>

#define S_LEN 2048
#define D_MODEL 1024
#define NH 16
#define HD 64
#define NB 2
#define NG 32

// Scratch (device globals: no allocations allowed)
__device__ float g_Q[NB * NH * S_LEN * HD];
__device__ float g_K[NB * NH * S_LEN * HD];
__device__ float g_V[NB * NH * S_LEN * HD];
__device__ float g_ctx[NB * S_LEN * D_MODEL];
__device__ int g_isg[S_LEN];
__device__ int g_gvalid[NG];

// ---------------------------------------------------------------------------
// Flags: is_global[s], plus dedup flags for global columns (duplicate indices
// in global_idx must be counted once in the softmax denominator).
// ---------------------------------------------------------------------------
__global__ void flags_kernel(const int* __restrict__ gidx) {
    int t = threadIdx.x;
    for (int s = t; s < S_LEN; s += blockDim.x) g_isg[s] = 0;
    __syncthreads();
    if (t < NG) {
        int g = gidx[t];
        g_isg[g] = 1;
        int v = 1;
        for (int w = 0; w < t; ++w)
            if (gidx[w] == g) v = 0;
        g_gvalid[t] = v;
    }
}

// ---------------------------------------------------------------------------
// GEMM: Y[m,n] = sum_k X[m,k] * W[n,k] + bias[n]
// BM=BN=64, BK=16, 256 threads, 4x4 micro-tile per thread.
// mode 0/1/2: write to g_Q/g_K/g_V in [B,H,S,HD] layout.
// mode 3: X = g_ctx (param ignored), write plain [M,N] to Yout.
// ---------------------------------------------------------------------------
__global__ __launch_bounds__(256) void gemm_kernel(
    const float* __restrict__ Xin, const float* __restrict__ W,
    const float* __restrict__ bias, float* __restrict__ Yout, int mode)
{
    __shared__ float As[16][64];  // [k][m]
    __shared__ float Bs[16][64];  // [k][n]

    const float* X = (mode == 3) ? g_ctx : Xin;
    int tid = threadIdx.x;
    int m0 = blockIdx.y * 64;
    int n0 = blockIdx.x * 64;
    int lr = tid >> 2;   // 0..63
    int lc = tid & 3;    // 0..3
    int ty = tid >> 4;   // 0..15 (m)
    int tx = tid & 15;   // 0..15 (n)

    float acc[4][4];
#pragma unroll
    for (int i = 0; i < 4; ++i)
#pragma unroll
        for (int j = 0; j < 4; ++j) acc[i][j] = 0.f;

    const float* Arow = X + (m0 + lr) * D_MODEL + lc * 4;
    const float* Brow = W + (n0 + lr) * D_MODEL + lc * 4;

    for (int k0 = 0; k0 < D_MODEL; k0 += 16) {
        float4 a = *(const float4*)(Arow + k0);
        float4 bb = *(const float4*)(Brow + k0);
        As[lc * 4 + 0][lr] = a.x;  As[lc * 4 + 1][lr] = a.y;
        As[lc * 4 + 2][lr] = a.z;  As[lc * 4 + 3][lr] = a.w;
        Bs[lc * 4 + 0][lr] = bb.x; Bs[lc * 4 + 1][lr] = bb.y;
        Bs[lc * 4 + 2][lr] = bb.z; Bs[lc * 4 + 3][lr] = bb.w;
        __syncthreads();
#pragma unroll
        for (int k = 0; k < 16; ++k) {
            float4 av = *(const float4*)&As[k][ty * 4];
            float4 bv = *(const float4*)&Bs[k][tx * 4];
            acc[0][0] += av.x * bv.x; acc[0][1] += av.x * bv.y;
            acc[0][2] += av.x * bv.z; acc[0][3] += av.x * bv.w;
            acc[1][0] += av.y * bv.x; acc[1][1] += av.y * bv.y;
            acc[1][2] += av.y * bv.z; acc[1][3] += av.y * bv.w;
            acc[2][0] += av.z * bv.x; acc[2][1] += av.z * bv.y;
            acc[2][2] += av.z * bv.z; acc[2][3] += av.z * bv.w;
            acc[3][0] += av.w * bv.x; acc[3][1] += av.w * bv.y;
            acc[3][2] += av.w * bv.z; acc[3][3] += av.w * bv.w;
        }
        __syncthreads();
    }

#pragma unroll
    for (int i = 0; i < 4; ++i) {
        int m = m0 + ty * 4 + i;
#pragma unroll
        for (int j = 0; j < 4; ++j) {
            int n = n0 + tx * 4 + j;
            float val = acc[i][j] + bias[n];
            if (mode == 3) {
                Yout[m * D_MODEL + n] = val;
            } else {
                int bb2 = m >> 11;
                int ss = m & (S_LEN - 1);
                int hh = n >> 6;
                int dd = n & 63;
                float* dst = (mode == 0) ? g_Q : (mode == 1) ? g_K : g_V;
                dst[((bb2 * NH + hh) * S_LEN + ss) * HD + dd] = val;
            }
        }
    }
}

// ---------------------------------------------------------------------------
// Attention. Grid: (65, H, B), 256 threads.
//  blockIdx.x in [0,64): parity tile t: parity = t&1, rows i0+2r, r=0..31,
//      i0 = (t>>1)*64 + (t&1). Col tiles: 17 local (parity) + 1 global-cols.
//  blockIdx.x == 64: global-row tile: rows = global_idx[0..31], 64 col tiles
//      covering all 2048 columns (mask fully true).
// No max-subtraction softmax (scores are O(1) here, exp-safe).
// ---------------------------------------------------------------------------
__global__ __launch_bounds__(256) void attn_kernel(const int* __restrict__ gidx)
{
    __shared__ float Qsm[32][65];      // [qrow][d]
    __shared__ float Kst[64 * 32];     // [d][j], XOR-swizzled in 16B units
    __shared__ float Vsm[32][64];      // [j][d]
    __shared__ float Psm[32][33];      // [qrow][j]
    __shared__ int gsh[NG];
    __shared__ int gval[NG];
    __shared__ int rowid[32];

    int tid = threadIdx.x;
    int h = blockIdx.y, b = blockIdx.z;
    int base = ((b * NH + h) * S_LEN) * HD;
    const float* Qb = g_Q + base;
    const float* Kb = g_K + base;
    const float* Vb = g_V + base;

    bool gtile = (blockIdx.x == 64);
    int qr = tid >> 3;   // 0..31: query row slot (also loader column slot)
    int sub = tid & 7;   // 0..7:  d-group / j-group

    if (tid < NG) { gsh[tid] = gidx[tid]; gval[tid] = g_gvalid[tid]; }
    __syncthreads();

    int i0 = 0;
    if (!gtile) {
        i0 = (blockIdx.x >> 1) * 64 + (blockIdx.x & 1);
        if (tid < 32) rowid[tid] = i0 + 2 * tid;
    } else {
        if (tid < 32) rowid[tid] = gsh[tid];
    }
    __syncthreads();

    int iq = rowid[qr];

    // Load Q rows into shared
    {
        float4 q1 = *(const float4*)&Qb[iq * HD + sub * 8];
        float4 q2 = *(const float4*)&Qb[iq * HD + sub * 8 + 4];
        Qsm[qr][sub * 8 + 0] = q1.x; Qsm[qr][sub * 8 + 1] = q1.y;
        Qsm[qr][sub * 8 + 2] = q1.z; Qsm[qr][sub * 8 + 3] = q1.w;
        Qsm[qr][sub * 8 + 4] = q2.x; Qsm[qr][sub * 8 + 5] = q2.y;
        Qsm[qr][sub * 8 + 6] = q2.z; Qsm[qr][sub * 8 + 7] = q2.w;
    }

    float acc[8];
#pragma unroll
    for (int u = 0; u < 8; ++u) acc[u] = 0.f;
    float rsum = 0.f;

    int nct = gtile ? 64 : 18;
    // K store swizzle base for this loader thread (column slot = qr, d-group = sub)
    int kswz = 4 * ((qr >> 2) ^ sub) + (qr & 3);

    for (int ct = 0; ct < nct; ++ct) {
        // ---- column index for loader (slot qr of this tile) ----
        int jcol;
        bool jvalid = true;
        if (gtile) {
            jcol = ct * 32 + qr;
        } else if (ct < 17) {
            jcol = i0 - 512 + 64 * ct + 2 * qr;
            jvalid = (jcol >= 0) && (jcol < S_LEN);
        } else {
            jcol = gsh[qr];
        }

        __syncthreads();  // previous tile's phase C done before overwrite

        if (jvalid) {
            float4 k1 = *(const float4*)&Kb[jcol * HD + sub * 8];
            float4 k2 = *(const float4*)&Kb[jcol * HD + sub * 8 + 4];
            Kst[(8 * sub + 0) * 32 + kswz] = k1.x;
            Kst[(8 * sub + 1) * 32 + kswz] = k1.y;
            Kst[(8 * sub + 2) * 32 + kswz] = k1.z;
            Kst[(8 * sub + 3) * 32 + kswz] = k1.w;
            Kst[(8 * sub + 4) * 32 + kswz] = k2.x;
            Kst[(8 * sub + 5) * 32 + kswz] = k2.y;
            Kst[(8 * sub + 6) * 32 + kswz] = k2.z;
            Kst[(8 * sub + 7) * 32 + kswz] = k2.w;
            float4 v1 = *(const float4*)&Vb[jcol * HD + sub * 8];
            float4 v2 = *(const float4*)&Vb[jcol * HD + sub * 8 + 4];
            *(float4*)&Vsm[qr][sub * 8] = v1;
            *(float4*)&Vsm[qr][sub * 8 + 4] = v2;
        } else {
#pragma unroll
            for (int u = 0; u < 8; ++u) Kst[(8 * sub + u) * 32 + kswz] = 0.f;
            float4 z = make_float4(0.f, 0.f, 0.f, 0.f);
            *(float4*)&Vsm[qr][sub * 8] = z;
            *(float4*)&Vsm[qr][sub * 8 + 4] = z;
        }
        __syncthreads();

        // ---- Phase A: scores for (row qr) x (cols 4*sub..4*sub+3) ----
        float sc0 = 0.f, sc1 = 0.f, sc2 = 0.f, sc3 = 0.f;
#pragma unroll
        for (int k = 0; k < 64; ++k) {
            float qv = Qsm[qr][k];
            float4 kv = *(const float4*)&Kst[k * 32 + 4 * (sub ^ (k >> 3))];
            sc0 += qv * kv.x; sc1 += qv * kv.y;
            sc2 += qv * kv.z; sc3 += qv * kv.w;
        }
        float scarr[4] = {sc0, sc1, sc2, sc3};
#pragma unroll
        for (int u = 0; u < 4; ++u) {
            int jj = 4 * sub + u;
            bool ok;
            if (gtile) {
                ok = true;  // global rows attend everything
            } else if (ct < 17) {
                int j = i0 - 512 + 64 * ct + 2 * jj;
                int d = j - iq;  // parity matches by construction
                ok = (j >= 0) && (j < S_LEN) && (d <= 512) && (d >= -512);
            } else {
                int j = gsh[jj];
                int d = j - iq;
                bool inloc = (d <= 512) && (d >= -512) && ((d & 1) == 0);
                ok = (gval[jj] != 0) && !inloc;  // dedup + already-counted-local
            }
            float p = ok ? __expf(scarr[u] * 0.125f) : 0.f;
            rsum += p;
            Psm[qr][jj] = p;
        }
        __syncthreads();

        // ---- Phase C: acc[d] += p * V  (d = {4*sub..+3} U {32+4*sub..+3}) ----
#pragma unroll 4
        for (int j = 0; j < 32; ++j) {
            float p = Psm[qr][j];
            float4 v1 = *(const float4*)&Vsm[j][4 * sub];
            float4 v2 = *(const float4*)&Vsm[j][32 + 4 * sub];
            acc[0] += p * v1.x; acc[1] += p * v1.y;
            acc[2] += p * v1.z; acc[3] += p * v1.w;
            acc[4] += p * v2.x; acc[5] += p * v2.y;
            acc[6] += p * v2.z; acc[7] += p * v2.w;
        }
    }

    // Row sum reduce across the 8 sub-threads of this row (aligned groups of 8)
    rsum += __shfl_xor_sync(0xffffffffu, rsum, 1);
    rsum += __shfl_xor_sync(0xffffffffu, rsum, 2);
    rsum += __shfl_xor_sync(0xffffffffu, rsum, 4);
    float inv = 1.f / rsum;

    // Parity tiles must not write global rows (the global-row tile owns them).
    bool wr = gtile || (g_isg[iq] == 0);
    if (wr) {
        float* dst = g_ctx + (b * S_LEN + iq) * D_MODEL + h * HD;
        float4 o1 = make_float4(acc[0] * inv, acc[1] * inv, acc[2] * inv, acc[3] * inv);
        float4 o2 = make_float4(acc[4] * inv, acc[5] * inv, acc[6] * inv, acc[7] * inv);
        *(float4*)&dst[4 * sub] = o1;
        *(float4*)&dst[32 + 4 * sub] = o2;
    }
}

// ---------------------------------------------------------------------------
extern "C" void kernel_launch(void* const* d_in, const int* in_sizes, int n_in,
                              void* d_out, int out_size) {
    const float* q  = (const float*)d_in[0];
    const float* k  = (const float*)d_in[1];
    const float* v  = (const float*)d_in[2];
    const float* Wq = (const float*)d_in[3];
    const float* Wk = (const float*)d_in[4];
    const float* Wv = (const float*)d_in[5];
    const float* Wo = (const float*)d_in[6];
    const float* bq = (const float*)d_in[7];
    const float* bk = (const float*)d_in[8];
    const float* bv = (const float*)d_in[9];
    const float* bo = (const float*)d_in[10];
    const int* gidx = (const int*)d_in[11];
    float* out = (float*)d_out;

    flags_kernel<<<1, 256>>>(gidx);

    dim3 gg(D_MODEL / 64, (NB * S_LEN) / 64);  // (16, 64)
    gemm_kernel<<<gg, 256>>>(q, Wq, bq, nullptr, 0);
    gemm_kernel<<<gg, 256>>>(k, Wk, bk, nullptr, 1);
    gemm_kernel<<<gg, 256>>>(v, Wv, bv, nullptr, 2);

    attn_kernel<<<dim3(65, NH, NB), 256>>>(gidx);

    gemm_kernel<<<gg, 256>>>(nullptr, Wo, bo, out, 3);
}

// round 4
// speedup vs baseline: 1.2807x; 1.2807x over previous
#include <cuda_runtime.h>

#define S_LEN 2048
#define D_MODEL 1024
#define NH 16
#define HD 64
#define NB 2
#define NG 32

// Scratch (device globals: no allocations allowed)
__device__ float g_Q[NB * NH * S_LEN * HD];
__device__ float g_K[NB * NH * S_LEN * HD];
__device__ float g_V[NB * NH * S_LEN * HD];
__device__ float g_ctx[NB * S_LEN * D_MODEL];
__device__ int g_isg[S_LEN];
__device__ int g_gvalid[NG];

// ---------------------------------------------------------------------------
// Flags: is_global[s], plus dedup flags for global columns (duplicate indices
// in global_idx must be counted once in the softmax denominator).
// ---------------------------------------------------------------------------
__global__ void flags_kernel(const int* __restrict__ gidx) {
    int t = threadIdx.x;
    for (int s = t; s < S_LEN; s += blockDim.x) g_isg[s] = 0;
    __syncthreads();
    if (t < NG) {
        int g = gidx[t];
        g_isg[g] = 1;
        int v = 1;
        for (int w = 0; w < t; ++w)
            if (gidx[w] == g) v = 0;
        g_gvalid[t] = v;
    }
}

// ---------------------------------------------------------------------------
// GEMM: Y[m,n] = sum_k X[m,k] * W[n,k] + bias[n]
// BM=BN=128, BK=8, 256 threads, 8x8 micro-tile (split 4+4), double-buffered
// smem, one __syncthreads per k-tile.
// mode -1: md = blockIdx.z in {0,1,2} -> write g_Q/g_K/g_V in [B,H,S,HD].
// mode  3: X = g_ctx, W/bias taken from the (Wv,bv) slots, write [M,N] Yout.
// ---------------------------------------------------------------------------
#define AP 132  // smem pitch (floats): conflict-free transposed STS + LDS.128

__global__ __launch_bounds__(256) void gemm128(
    const float* __restrict__ Xq, const float* __restrict__ Xk,
    const float* __restrict__ Xv,
    const float* __restrict__ Wq, const float* __restrict__ Wk,
    const float* __restrict__ Wv,
    const float* __restrict__ bq, const float* __restrict__ bk,
    const float* __restrict__ bv,
    float* __restrict__ Yout, int mode)
{
    __shared__ float As[2][8 * AP];
    __shared__ float Bs[2][8 * AP];

    int md = (mode < 0) ? (int)blockIdx.z : mode;
    const float* X = (md == 0) ? Xq : (md == 1) ? Xk : (md == 2) ? Xv : g_ctx;
    const float* W = (md == 0) ? Wq : (md == 1) ? Wk : Wv;
    const float* bias = (md == 0) ? bq : (md == 1) ? bk : bv;

    int tid = threadIdx.x;
    int m0 = blockIdx.y * 128;
    int n0 = blockIdx.x * 128;
    int r  = tid >> 1;         // 0..127 (tile row for loads)
    int kc = (tid & 1) * 4;    // 0 or 4 (k offset for loads)
    int ty = tid >> 4;         // 0..15 (m micro)
    int tx = tid & 15;         // 0..15 (n micro)

    const float* Aptr = X + (m0 + r) * D_MODEL + kc;
    const float* Bptr = W + (n0 + r) * D_MODEL + kc;

    float acc[8][8];
#pragma unroll
    for (int i = 0; i < 8; ++i)
#pragma unroll
        for (int j = 0; j < 8; ++j) acc[i][j] = 0.f;

    float4 a = *(const float4*)Aptr;
    float4 b = *(const float4*)Bptr;
    {
        float* as = As[0]; float* bs = Bs[0];
        as[(kc + 0) * AP + r] = a.x; as[(kc + 1) * AP + r] = a.y;
        as[(kc + 2) * AP + r] = a.z; as[(kc + 3) * AP + r] = a.w;
        bs[(kc + 0) * AP + r] = b.x; bs[(kc + 1) * AP + r] = b.y;
        bs[(kc + 2) * AP + r] = b.z; bs[(kc + 3) * AP + r] = b.w;
    }
    __syncthreads();

    const int NT = D_MODEL / 8;  // 128 k-tiles
    for (int t = 0; t < NT; ++t) {
        if (t < NT - 1) {
            a = *(const float4*)(Aptr + (t + 1) * 8);
            b = *(const float4*)(Bptr + (t + 1) * 8);
        }
        const float* as = As[t & 1];
        const float* bs = Bs[t & 1];
#pragma unroll
        for (int k = 0; k < 8; ++k) {
            float4 a0 = *(const float4*)&as[k * AP + ty * 4];
            float4 a1 = *(const float4*)&as[k * AP + 64 + ty * 4];
            float4 b0 = *(const float4*)&bs[k * AP + tx * 4];
            float4 b1 = *(const float4*)&bs[k * AP + 64 + tx * 4];
            float av[8] = {a0.x, a0.y, a0.z, a0.w, a1.x, a1.y, a1.z, a1.w};
            float bv8[8] = {b0.x, b0.y, b0.z, b0.w, b1.x, b1.y, b1.z, b1.w};
#pragma unroll
            for (int i = 0; i < 8; ++i)
#pragma unroll
                for (int j = 0; j < 8; ++j) acc[i][j] += av[i] * bv8[j];
        }
        if (t < NT - 1) {
            float* asn = As[(t + 1) & 1]; float* bsn = Bs[(t + 1) & 1];
            asn[(kc + 0) * AP + r] = a.x; asn[(kc + 1) * AP + r] = a.y;
            asn[(kc + 2) * AP + r] = a.z; asn[(kc + 3) * AP + r] = a.w;
            bsn[(kc + 0) * AP + r] = b.x; bsn[(kc + 1) * AP + r] = b.y;
            bsn[(kc + 2) * AP + r] = b.z; bsn[(kc + 3) * AP + r] = b.w;
            __syncthreads();
        }
    }

    float4 bias0 = *(const float4*)&bias[n0 + tx * 4];
    float4 bias1 = *(const float4*)&bias[n0 + 64 + tx * 4];
    float bb[8] = {bias0.x, bias0.y, bias0.z, bias0.w,
                   bias1.x, bias1.y, bias1.z, bias1.w};

#pragma unroll
    for (int i = 0; i < 8; ++i) {
        int m = m0 + ((i < 4) ? (ty * 4 + i) : (64 + ty * 4 + (i - 4)));
        if (md == 3) {
            float4 o0 = make_float4(acc[i][0] + bb[0], acc[i][1] + bb[1],
                                    acc[i][2] + bb[2], acc[i][3] + bb[3]);
            float4 o1 = make_float4(acc[i][4] + bb[4], acc[i][5] + bb[5],
                                    acc[i][6] + bb[6], acc[i][7] + bb[7]);
            *(float4*)&Yout[m * D_MODEL + n0 + tx * 4] = o0;
            *(float4*)&Yout[m * D_MODEL + n0 + 64 + tx * 4] = o1;
        } else {
            float* dst = (md == 0) ? g_Q : (md == 1) ? g_K : g_V;
            int b2 = m >> 11;
            int ss = m & (S_LEN - 1);
#pragma unroll
            for (int jh = 0; jh < 2; ++jh) {
                int n = n0 + jh * 64 + tx * 4;
                int hh = n >> 6;
                int dd = n & 63;
                float4 o = make_float4(acc[i][jh * 4 + 0] + bb[jh * 4 + 0],
                                       acc[i][jh * 4 + 1] + bb[jh * 4 + 1],
                                       acc[i][jh * 4 + 2] + bb[jh * 4 + 2],
                                       acc[i][jh * 4 + 3] + bb[jh * 4 + 3]);
                *(float4*)&dst[((b2 * NH + hh) * S_LEN + ss) * HD + dd] = o;
            }
        }
    }
}

// ---------------------------------------------------------------------------
// Attention. Grid: (65, H, B), 256 threads.
//  blockIdx.x in [0,64): parity tile; rows i0+2r. Local col tiles clipped to
//  the valid range [ct_begin, ct_last] (+1 deduplicated global-column tile).
//  blockIdx.x == 64: global-row tile: rows = global_idx, 64 col tiles.
// No max-subtraction softmax (scores are O(1) here, exp-safe).
// ---------------------------------------------------------------------------
__global__ __launch_bounds__(256) void attn_kernel(const int* __restrict__ gidx)
{
    __shared__ float Qsm[32][65];      // [qrow][d]
    __shared__ float Kst[64 * 32];     // [d][j], XOR-swizzled in 16B units
    __shared__ float Vsm[32][64];      // [j][d]
    __shared__ float Psm[32][33];      // [qrow][j]
    __shared__ int gsh[NG];
    __shared__ int gval[NG];
    __shared__ int rowid[32];

    int tid = threadIdx.x;
    int h = blockIdx.y, b = blockIdx.z;
    int base = ((b * NH + h) * S_LEN) * HD;
    const float* Qb = g_Q + base;
    const float* Kb = g_K + base;
    const float* Vb = g_V + base;

    bool gtile = (blockIdx.x == 64);
    int qr = tid >> 3;   // 0..31: query row slot (also loader column slot)
    int sub = tid & 7;   // 0..7:  d-group / j-group

    if (tid < NG) { gsh[tid] = gidx[tid]; gval[tid] = g_gvalid[tid]; }
    __syncthreads();

    int i0 = 0;
    if (!gtile) {
        i0 = (blockIdx.x >> 1) * 64 + (blockIdx.x & 1);
        if (tid < 32) rowid[tid] = i0 + 2 * tid;
    } else {
        if (tid < 32) rowid[tid] = gsh[tid];
    }
    __syncthreads();

    int iq = rowid[qr];

    // Load Q rows into shared
    {
        float4 q1 = *(const float4*)&Qb[iq * HD + sub * 8];
        float4 q2 = *(const float4*)&Qb[iq * HD + sub * 8 + 4];
        Qsm[qr][sub * 8 + 0] = q1.x; Qsm[qr][sub * 8 + 1] = q1.y;
        Qsm[qr][sub * 8 + 2] = q1.z; Qsm[qr][sub * 8 + 3] = q1.w;
        Qsm[qr][sub * 8 + 4] = q2.x; Qsm[qr][sub * 8 + 5] = q2.y;
        Qsm[qr][sub * 8 + 6] = q2.z; Qsm[qr][sub * 8 + 7] = q2.w;
    }

    float acc[8];
#pragma unroll
    for (int u = 0; u < 8; ++u) acc[u] = 0.f;
    float rsum = 0.f;

    // Valid local-tile range: tile ct covers j in [i0-512+64ct, i0-512+64ct+62]
    int ct_begin = 0, ntile;
    if (gtile) {
        ntile = 64;
    } else {
        int cb = (450 - i0 + 63) >> 6;     // ceil((450 - i0)/64)
        if (cb < 0) cb = 0;
        int cl = (2559 - i0) >> 6;         // last tile with first col <= 2047
        if (cl > 16) cl = 16;
        ct_begin = cb;
        ntile = (cl - cb + 1) + 1;         // + global-column tile
    }

    // K store swizzle base for this loader thread (column slot = qr, d-group = sub)
    int kswz = 4 * ((qr >> 2) ^ sub) + (qr & 3);

    for (int ci = 0; ci < ntile; ++ci) {
        int ct = gtile ? ci : ((ci == ntile - 1) ? 17 : (ct_begin + ci));

        // ---- column index for loader (slot qr of this tile) ----
        int jcol;
        bool jvalid = true;
        if (gtile) {
            jcol = ct * 32 + qr;
        } else if (ct < 17) {
            jcol = i0 - 512 + 64 * ct + 2 * qr;
            jvalid = (jcol >= 0) && (jcol < S_LEN);
        } else {
            jcol = gsh[qr];
        }

        __syncthreads();  // previous tile's phase C done before overwrite

        if (jvalid) {
            float4 k1 = *(const float4*)&Kb[jcol * HD + sub * 8];
            float4 k2 = *(const float4*)&Kb[jcol * HD + sub * 8 + 4];
            Kst[(8 * sub + 0) * 32 + kswz] = k1.x;
            Kst[(8 * sub + 1) * 32 + kswz] = k1.y;
            Kst[(8 * sub + 2) * 32 + kswz] = k1.z;
            Kst[(8 * sub + 3) * 32 + kswz] = k1.w;
            Kst[(8 * sub + 4) * 32 + kswz] = k2.x;
            Kst[(8 * sub + 5) * 32 + kswz] = k2.y;
            Kst[(8 * sub + 6) * 32 + kswz] = k2.z;
            Kst[(8 * sub + 7) * 32 + kswz] = k2.w;
            float4 v1 = *(const float4*)&Vb[jcol * HD + sub * 8];
            float4 v2 = *(const float4*)&Vb[jcol * HD + sub * 8 + 4];
            *(float4*)&Vsm[qr][sub * 8] = v1;
            *(float4*)&Vsm[qr][sub * 8 + 4] = v2;
        } else {
#pragma unroll
            for (int u = 0; u < 8; ++u) Kst[(8 * sub + u) * 32 + kswz] = 0.f;
            float4 z = make_float4(0.f, 0.f, 0.f, 0.f);
            *(float4*)&Vsm[qr][sub * 8] = z;
            *(float4*)&Vsm[qr][sub * 8 + 4] = z;
        }
        __syncthreads();

        // ---- Phase A: scores for (row qr) x (cols 4*sub..4*sub+3) ----
        float sc0 = 0.f, sc1 = 0.f, sc2 = 0.f, sc3 = 0.f;
#pragma unroll
        for (int k = 0; k < 64; ++k) {
            float qv = Qsm[qr][k];
            float4 kv = *(const float4*)&Kst[k * 32 + 4 * (sub ^ (k >> 3))];
            sc0 += qv * kv.x; sc1 += qv * kv.y;
            sc2 += qv * kv.z; sc3 += qv * kv.w;
        }
        float scarr[4] = {sc0, sc1, sc2, sc3};
#pragma unroll
        for (int u = 0; u < 4; ++u) {
            int jj = 4 * sub + u;
            bool ok;
            if (gtile) {
                ok = true;  // global rows attend everything
            } else if (ct < 17) {
                int j = i0 - 512 + 64 * ct + 2 * jj;
                int d = j - iq;  // parity matches by construction
                ok = (j >= 0) && (j < S_LEN) && (d <= 512) && (d >= -512);
            } else {
                int j = gsh[jj];
                int d = j - iq;
                bool inloc = (d <= 512) && (d >= -512) && ((d & 1) == 0);
                ok = (gval[jj] != 0) && !inloc;  // dedup + already-counted-local
            }
            float p = ok ? __expf(scarr[u] * 0.125f) : 0.f;
            rsum += p;
            Psm[qr][jj] = p;
        }
        __syncthreads();

        // ---- Phase C: acc[d] += p * V  (d = {4*sub..+3} U {32+4*sub..+3}) ----
#pragma unroll 4
        for (int j = 0; j < 32; ++j) {
            float p = Psm[qr][j];
            float4 v1 = *(const float4*)&Vsm[j][4 * sub];
            float4 v2 = *(const float4*)&Vsm[j][32 + 4 * sub];
            acc[0] += p * v1.x; acc[1] += p * v1.y;
            acc[2] += p * v1.z; acc[3] += p * v1.w;
            acc[4] += p * v2.x; acc[5] += p * v2.y;
            acc[6] += p * v2.z; acc[7] += p * v2.w;
        }
    }

    // Row sum reduce across the 8 sub-threads of this row (aligned groups of 8)
    rsum += __shfl_xor_sync(0xffffffffu, rsum, 1);
    rsum += __shfl_xor_sync(0xffffffffu, rsum, 2);
    rsum += __shfl_xor_sync(0xffffffffu, rsum, 4);
    float inv = 1.f / rsum;

    // Parity tiles must not write global rows (the global-row tile owns them).
    bool wr = gtile || (g_isg[iq] == 0);
    if (wr) {
        float* dst = g_ctx + (b * S_LEN + iq) * D_MODEL + h * HD;
        float4 o1 = make_float4(acc[0] * inv, acc[1] * inv, acc[2] * inv, acc[3] * inv);
        float4 o2 = make_float4(acc[4] * inv, acc[5] * inv, acc[6] * inv, acc[7] * inv);
        *(float4*)&dst[4 * sub] = o1;
        *(float4*)&dst[32 + 4 * sub] = o2;
    }
}

// ---------------------------------------------------------------------------
extern "C" void kernel_launch(void* const* d_in, const int* in_sizes, int n_in,
                              void* d_out, int out_size) {
    const float* q  = (const float*)d_in[0];
    const float* k  = (const float*)d_in[1];
    const float* v  = (const float*)d_in[2];
    const float* Wq = (const float*)d_in[3];
    const float* Wk = (const float*)d_in[4];
    const float* Wv = (const float*)d_in[5];
    const float* Wo = (const float*)d_in[6];
    const float* bq = (const float*)d_in[7];
    const float* bk = (const float*)d_in[8];
    const float* bv = (const float*)d_in[9];
    const float* bo = (const float*)d_in[10];
    const int* gidx = (const int*)d_in[11];
    float* out = (float*)d_out;

    flags_kernel<<<1, 256>>>(gidx);

    // Fused QKV projection: grid z selects Q/K/V.
    dim3 gqkv(D_MODEL / 128, (NB * S_LEN) / 128, 3);  // (8, 32, 3)
    gemm128<<<gqkv, 256>>>(q, k, v, Wq, Wk, Wv, bq, bk, bv, nullptr, -1);

    attn_kernel<<<dim3(65, NH, NB), 256>>>(gidx);

    // Output projection: Wo/bo ride in the (Wv,bv) slots for mode 3.
    dim3 go(D_MODEL / 128, (NB * S_LEN) / 128);       // (8, 32)
    gemm128<<<go, 256>>>(nullptr, nullptr, nullptr,
                         Wq, Wk, Wo, bq, bk, bo, out, 3);
}

// round 9
// speedup vs baseline: 1.6706x; 1.3045x over previous
#include <cuda_runtime.h>
#include <cuda_bf16.h>
#include <cstdint>

#define S_LEN 2048
#define D_MODEL 1024
#define NH 16
#define HD 64
#define NB 2
#define NG 32
#define SN (NB * S_LEN)                 // 4096 rows of X
#define XELE (SN * D_MODEL)             // 4,194,304
#define WELE (D_MODEL * D_MODEL)        // 1,048,576
#define TOT_SPLIT (3 * XELE + 4 * WELE) // 16,777,216

// ---------------------------------------------------------------------------
// Scratch (device globals: no allocations allowed)
// ---------------------------------------------------------------------------
__device__ float g_Q[NB * NH * S_LEN * HD];
__device__ float g_K[NB * NH * S_LEN * HD];
__device__ float g_V[NB * NH * S_LEN * HD];
__device__ float g_ctx[NB * S_LEN * D_MODEL];
__device__ int g_isg[S_LEN];
__device__ int g_gvalid[NG];
// bf16 hi/lo splits: [q | k | v | Wq | Wk | Wv | Wo]
__device__ __nv_bfloat16 g_BH[TOT_SPLIT];
__device__ __nv_bfloat16 g_BL[TOT_SPLIT];
// ctx split (for the output projection)
__device__ __nv_bfloat16 g_CH[XELE];
__device__ __nv_bfloat16 g_CL[XELE];

// ---------------------------------------------------------------------------
__device__ __forceinline__ uint32_t smem_u32(const void* p) {
    uint32_t a;
    asm("{ .reg .u64 t; cvta.to.shared.u64 t, %1; cvt.u32.u64 %0, t; }"
        : "=r"(a) : "l"(p));
    return a;
}

#define LDM4(R, ADDR) \
    asm volatile("ldmatrix.sync.aligned.m8n8.x4.shared.b16 {%0,%1,%2,%3}, [%4];" \
        : "=r"((R)[0]), "=r"((R)[1]), "=r"((R)[2]), "=r"((R)[3]) : "r"(ADDR))

#define MMA16816(C, A, B0, B1) \
    asm volatile("mma.sync.aligned.m16n8k16.row.col.f32.bf16.bf16.f32 " \
        "{%0,%1,%2,%3}, {%4,%5,%6,%7}, {%8,%9}, {%0,%1,%2,%3};" \
        : "+f"((C)[0]), "+f"((C)[1]), "+f"((C)[2]), "+f"((C)[3]) \
        : "r"((A)[0]), "r"((A)[1]), "r"((A)[2]), "r"((A)[3]), "r"(B0), "r"(B1))

// ---------------------------------------------------------------------------
// Flags
// ---------------------------------------------------------------------------
__global__ void flags_kernel(const int* __restrict__ gidx) {
    int t = threadIdx.x;
    for (int s = t; s < S_LEN; s += blockDim.x) g_isg[s] = 0;
    __syncthreads();
    if (t < NG) {
        int g = gidx[t];
        g_isg[g] = 1;
        int v = 1;
        for (int w = 0; w < t; ++w)
            if (gidx[w] == g) v = 0;
        g_gvalid[t] = v;
    }
}

// ---------------------------------------------------------------------------
// bf16 hi/lo split of q,k,v,Wq,Wk,Wv,Wo into the flat g_BH/g_BL arrays
// ---------------------------------------------------------------------------
__device__ __forceinline__ void split4(float4 x, __nv_bfloat16* h, __nv_bfloat16* l) {
    float xs[4] = {x.x, x.y, x.z, x.w};
#pragma unroll
    for (int i = 0; i < 4; ++i) {
        __nv_bfloat16 hi = __float2bfloat16(xs[i]);
        h[i] = hi;
        l[i] = __float2bfloat16(xs[i] - __bfloat162float(hi));
    }
}

__global__ __launch_bounds__(256) void split_main(
    const float* __restrict__ q, const float* __restrict__ k,
    const float* __restrict__ v, const float* __restrict__ wq,
    const float* __restrict__ wk, const float* __restrict__ wv,
    const float* __restrict__ wo)
{
    int n4 = TOT_SPLIT / 4;
    for (int i = blockIdx.x * blockDim.x + threadIdx.x; i < n4;
         i += gridDim.x * blockDim.x) {
        int e = i * 4;
        const float* src;
        if (e < XELE) src = q + e;
        else if (e < 2 * XELE) src = k + (e - XELE);
        else if (e < 3 * XELE) src = v + (e - 2 * XELE);
        else {
            int o = e - 3 * XELE;
            int w = o / WELE;
            int off = o - w * WELE;
            src = ((w == 0) ? wq : (w == 1) ? wk : (w == 2) ? wv : wo) + off;
        }
        float4 x = *(const float4*)src;
        __nv_bfloat16 h[4], l[4];
        split4(x, h, l);
        *(uint2*)&g_BH[e] = *(uint2*)h;
        *(uint2*)&g_BL[e] = *(uint2*)l;
    }
}

__global__ __launch_bounds__(256) void split_ctx() {
    int n4 = XELE / 4;
    for (int i = blockIdx.x * blockDim.x + threadIdx.x; i < n4;
         i += gridDim.x * blockDim.x) {
        int e = i * 4;
        float4 x = *(const float4*)&g_ctx[e];
        __nv_bfloat16 h[4], l[4];
        split4(x, h, l);
        *(uint2*)&g_CH[e] = *(uint2*)h;
        *(uint2*)&g_CL[e] = *(uint2*)l;
    }
}

// ---------------------------------------------------------------------------
// mma.sync GEMM: Y[m,n] = sum_k X[m,k]*W[n,k] + bias[n], fp32 via bf16x3.
// BM=128, BN=64, BK=64. 8 warps, warp tile 32x32. SW128-style swizzled smem
// (128B rows, unit ^ (row&7)), ldmatrix fragments, double-buffered stages.
// mode -1: md = blockIdx.z in {0,1,2} -> scatter to g_Q/g_K/g_V [B,H,S,HD].
// mode  3: X = ctx split, W = Wo split, write [M,N] to Yout.
// Stage layout (49152 B): [Ah 16K | Al 16K | Bh 8K | Bl 8K]
// ---------------------------------------------------------------------------
#define STAGE 49152
#define GEMM_SMEM (2 * STAGE)

__global__ __launch_bounds__(256) void gemm_mma(
    int mode, float* __restrict__ Yout,
    const float* __restrict__ b0p, const float* __restrict__ b1p,
    const float* __restrict__ b2p)
{
    extern __shared__ __align__(128) char smc[];
    const uint32_t smem_base = smem_u32(smc);

    int md = (mode < 0) ? (int)blockIdx.z : 3;
    const __nv_bfloat16 *Ah, *Al, *Bh, *Bl;
    const float* bias;
    if (md < 3) {
        Ah = g_BH + (size_t)md * XELE;
        Al = g_BL + (size_t)md * XELE;
        Bh = g_BH + 3 * (size_t)XELE + (size_t)md * WELE;
        Bl = g_BL + 3 * (size_t)XELE + (size_t)md * WELE;
        bias = (md == 0) ? b0p : (md == 1) ? b1p : b2p;
    } else {
        Ah = g_CH; Al = g_CL;
        Bh = g_BH + 3 * (size_t)XELE + 3 * (size_t)WELE;
        Bl = g_BL + 3 * (size_t)XELE + 3 * (size_t)WELE;
        bias = b2p;
    }

    int tid = threadIdx.x;
    int lane = tid & 31, wid = tid >> 5;
    int warp_m = wid & 3, warp_n = wid >> 2;
    int m0 = blockIdx.y * 128, n0 = blockIdx.x * 64;

    // ---- loader mapping ----
    int rA = tid >> 1;            // 0..127
    int cA = (tid & 1) * 4;       // 16B-unit base (of 8)
    int rB = tid >> 2;            // 0..63
    int cB = (tid & 3) * 2;

    const __nv_bfloat16* gAh = Ah + (size_t)(m0 + rA) * D_MODEL;
    const __nv_bfloat16* gAl = Al + (size_t)(m0 + rA) * D_MODEL;
    const __nv_bfloat16* gBh = Bh + (size_t)(n0 + rB) * D_MODEL;
    const __nv_bfloat16* gBl = Bl + (size_t)(n0 + rB) * D_MODEL;

    uint32_t stAo[4], stBo[2];
#pragma unroll
    for (int u = 0; u < 4; ++u)
        stAo[u] = (uint32_t)rA * 128u + (uint32_t)(((cA + u) ^ (rA & 7)) * 16);
#pragma unroll
    for (int u = 0; u < 2; ++u)
        stBo[u] = 32768u + (uint32_t)rB * 128u +
                  (uint32_t)(((cB + u) ^ (rB & 7)) * 16);

    // ---- fragment (ldmatrix) address components ----
    uint32_t aA_off = (uint32_t)(warp_m * 32 + (lane & 15)) * 128u;
    int aA_hi = lane >> 4;
    int lsw = lane & 7;
    uint32_t aB_off = (uint32_t)(warp_n * 32 + ((lane >> 4) << 3) + (lane & 7)) * 128u;
    int aB_hi = (lane >> 3) & 1;

    float acc[2][4][4];
#pragma unroll
    for (int i = 0; i < 2; ++i)
#pragma unroll
        for (int j = 0; j < 4; ++j)
#pragma unroll
            for (int c = 0; c < 4; ++c) acc[i][j][c] = 0.f;

    uint4 va[4], vla[4], vb[2], vlb[2];

    // prologue: load stage 0
#pragma unroll
    for (int u = 0; u < 4; ++u) {
        va[u]  = *(const uint4*)(gAh + (cA + u) * 8);
        vla[u] = *(const uint4*)(gAl + (cA + u) * 8);
    }
#pragma unroll
    for (int u = 0; u < 2; ++u) {
        vb[u]  = *(const uint4*)(gBh + (cB + u) * 8);
        vlb[u] = *(const uint4*)(gBl + (cB + u) * 8);
    }
    {
        char* base = smc;
#pragma unroll
        for (int u = 0; u < 4; ++u) {
            *(uint4*)(base + stAo[u]) = va[u];
            *(uint4*)(base + 16384 + stAo[u]) = vla[u];
        }
#pragma unroll
        for (int u = 0; u < 2; ++u) {
            *(uint4*)(base + stBo[u]) = vb[u];
            *(uint4*)(base + 8192 + stBo[u]) = vlb[u];
        }
    }
    __syncthreads();

    const int NCH = D_MODEL / 64;  // 16
    for (int ci = 0; ci < NCH; ++ci) {
        if (ci < NCH - 1) {
            int kb = (ci + 1) * 64;
#pragma unroll
            for (int u = 0; u < 4; ++u) {
                va[u]  = *(const uint4*)(gAh + kb + (cA + u) * 8);
                vla[u] = *(const uint4*)(gAl + kb + (cA + u) * 8);
            }
#pragma unroll
            for (int u = 0; u < 2; ++u) {
                vb[u]  = *(const uint4*)(gBh + kb + (cB + u) * 8);
                vlb[u] = *(const uint4*)(gBl + kb + (cB + u) * 8);
            }
        }

        uint32_t sb = smem_base + (uint32_t)(ci & 1) * STAGE;
#pragma unroll
        for (int ks = 0; ks < 4; ++ks) {
            uint32_t swA = (uint32_t)(((ks * 2 + aA_hi) ^ lsw) * 16);
            uint32_t swB = (uint32_t)(((ks * 2 + aB_hi) ^ lsw) * 16);
            uint32_t ah[2][4], al_[2][4], bh[2][4], bl_[2][4];
#pragma unroll
            for (int mt = 0; mt < 2; ++mt) {
                LDM4(ah[mt],  sb + aA_off + mt * 2048 + swA);
                LDM4(al_[mt], sb + 16384 + aA_off + mt * 2048 + swA);
            }
#pragma unroll
            for (int nb = 0; nb < 2; ++nb) {
                LDM4(bh[nb],  sb + 32768 + aB_off + nb * 2048 + swB);
                LDM4(bl_[nb], sb + 40960 + aB_off + nb * 2048 + swB);
            }
#pragma unroll
            for (int mt = 0; mt < 2; ++mt) {
#pragma unroll
                for (int nt = 0; nt < 4; ++nt) {
                    int nb = nt >> 1, hp = (nt & 1) * 2;
                    MMA16816(acc[mt][nt], ah[mt], bh[nb][hp], bh[nb][hp + 1]);
                    MMA16816(acc[mt][nt], ah[mt], bl_[nb][hp], bl_[nb][hp + 1]);
                    MMA16816(acc[mt][nt], al_[mt], bh[nb][hp], bh[nb][hp + 1]);
                }
            }
        }

        if (ci < NCH - 1) {
            char* base = smc + ((ci + 1) & 1) * STAGE;
#pragma unroll
            for (int u = 0; u < 4; ++u) {
                *(uint4*)(base + stAo[u]) = va[u];
                *(uint4*)(base + 16384 + stAo[u]) = vla[u];
            }
#pragma unroll
            for (int u = 0; u < 2; ++u) {
                *(uint4*)(base + stBo[u]) = vb[u];
                *(uint4*)(base + 8192 + stBo[u]) = vlb[u];
            }
        }
        __syncthreads();
    }

    // ---- epilogue ----
    int g = lane >> 2, c2 = (lane & 3) * 2;
#pragma unroll
    for (int mt = 0; mt < 2; ++mt) {
#pragma unroll
        for (int nt = 0; nt < 4; ++nt) {
            int m = m0 + warp_m * 32 + mt * 16 + g;
            int n = n0 + warp_n * 32 + nt * 8 + c2;
            float2 bs = *(const float2*)&bias[n];
            float2 lo = make_float2(acc[mt][nt][0] + bs.x, acc[mt][nt][1] + bs.y);
            float2 hi = make_float2(acc[mt][nt][2] + bs.x, acc[mt][nt][3] + bs.y);
            if (md == 3) {
                *(float2*)&Yout[(size_t)m * D_MODEL + n] = lo;
                *(float2*)&Yout[(size_t)(m + 8) * D_MODEL + n] = hi;
            } else {
                float* dst = (md == 0) ? g_Q : (md == 1) ? g_K : g_V;
                int hh = n >> 6, dd = n & 63;
                int b2a = m >> 11, ssa = m & (S_LEN - 1);
                int b2b = (m + 8) >> 11, ssb = (m + 8) & (S_LEN - 1);
                *(float2*)&dst[(((size_t)b2a * NH + hh) * S_LEN + ssa) * HD + dd] = lo;
                *(float2*)&dst[(((size_t)b2b * NH + hh) * S_LEN + ssb) * HD + dd] = hi;
            }
        }
    }
}

// ---------------------------------------------------------------------------
// Attention (unchanged from R3). Grid: (65, H, B), 256 threads.
// ---------------------------------------------------------------------------
__global__ __launch_bounds__(256) void attn_kernel(const int* __restrict__ gidx)
{
    __shared__ float Qsm[32][65];
    __shared__ float Kst[64 * 32];
    __shared__ float Vsm[32][64];
    __shared__ float Psm[32][33];
    __shared__ int gsh[NG];
    __shared__ int gval[NG];
    __shared__ int rowid[32];

    int tid = threadIdx.x;
    int h = blockIdx.y, b = blockIdx.z;
    int base = ((b * NH + h) * S_LEN) * HD;
    const float* Qb = g_Q + base;
    const float* Kb = g_K + base;
    const float* Vb = g_V + base;

    bool gtile = (blockIdx.x == 64);
    int qr = tid >> 3;
    int sub = tid & 7;

    if (tid < NG) { gsh[tid] = gidx[tid]; gval[tid] = g_gvalid[tid]; }
    __syncthreads();

    int i0 = 0;
    if (!gtile) {
        i0 = (blockIdx.x >> 1) * 64 + (blockIdx.x & 1);
        if (tid < 32) rowid[tid] = i0 + 2 * tid;
    } else {
        if (tid < 32) rowid[tid] = gsh[tid];
    }
    __syncthreads();

    int iq = rowid[qr];

    {
        float4 q1 = *(const float4*)&Qb[iq * HD + sub * 8];
        float4 q2 = *(const float4*)&Qb[iq * HD + sub * 8 + 4];
        Qsm[qr][sub * 8 + 0] = q1.x; Qsm[qr][sub * 8 + 1] = q1.y;
        Qsm[qr][sub * 8 + 2] = q1.z; Qsm[qr][sub * 8 + 3] = q1.w;
        Qsm[qr][sub * 8 + 4] = q2.x; Qsm[qr][sub * 8 + 5] = q2.y;
        Qsm[qr][sub * 8 + 6] = q2.z; Qsm[qr][sub * 8 + 7] = q2.w;
    }

    float acc[8];
#pragma unroll
    for (int u = 0; u < 8; ++u) acc[u] = 0.f;
    float rsum = 0.f;

    int ct_begin = 0, ntile;
    if (gtile) {
        ntile = 64;
    } else {
        int cb = (450 - i0 + 63) >> 6;
        if (cb < 0) cb = 0;
        int cl = (2559 - i0) >> 6;
        if (cl > 16) cl = 16;
        ct_begin = cb;
        ntile = (cl - cb + 1) + 1;
    }

    int kswz = 4 * ((qr >> 2) ^ sub) + (qr & 3);

    for (int ci = 0; ci < ntile; ++ci) {
        int ct = gtile ? ci : ((ci == ntile - 1) ? 17 : (ct_begin + ci));

        int jcol;
        bool jvalid = true;
        if (gtile) {
            jcol = ct * 32 + qr;
        } else if (ct < 17) {
            jcol = i0 - 512 + 64 * ct + 2 * qr;
            jvalid = (jcol >= 0) && (jcol < S_LEN);
        } else {
            jcol = gsh[qr];
        }

        __syncthreads();

        if (jvalid) {
            float4 k1 = *(const float4*)&Kb[jcol * HD + sub * 8];
            float4 k2 = *(const float4*)&Kb[jcol * HD + sub * 8 + 4];
            Kst[(8 * sub + 0) * 32 + kswz] = k1.x;
            Kst[(8 * sub + 1) * 32 + kswz] = k1.y;
            Kst[(8 * sub + 2) * 32 + kswz] = k1.z;
            Kst[(8 * sub + 3) * 32 + kswz] = k1.w;
            Kst[(8 * sub + 4) * 32 + kswz] = k2.x;
            Kst[(8 * sub + 5) * 32 + kswz] = k2.y;
            Kst[(8 * sub + 6) * 32 + kswz] = k2.z;
            Kst[(8 * sub + 7) * 32 + kswz] = k2.w;
            float4 v1 = *(const float4*)&Vb[jcol * HD + sub * 8];
            float4 v2 = *(const float4*)&Vb[jcol * HD + sub * 8 + 4];
            *(float4*)&Vsm[qr][sub * 8] = v1;
            *(float4*)&Vsm[qr][sub * 8 + 4] = v2;
        } else {
#pragma unroll
            for (int u = 0; u < 8; ++u) Kst[(8 * sub + u) * 32 + kswz] = 0.f;
            float4 z = make_float4(0.f, 0.f, 0.f, 0.f);
            *(float4*)&Vsm[qr][sub * 8] = z;
            *(float4*)&Vsm[qr][sub * 8 + 4] = z;
        }
        __syncthreads();

        float sc0 = 0.f, sc1 = 0.f, sc2 = 0.f, sc3 = 0.f;
#pragma unroll
        for (int k = 0; k < 64; ++k) {
            float qv = Qsm[qr][k];
            float4 kv = *(const float4*)&Kst[k * 32 + 4 * (sub ^ (k >> 3))];
            sc0 += qv * kv.x; sc1 += qv * kv.y;
            sc2 += qv * kv.z; sc3 += qv * kv.w;
        }
        float scarr[4] = {sc0, sc1, sc2, sc3};
#pragma unroll
        for (int u = 0; u < 4; ++u) {
            int jj = 4 * sub + u;
            bool ok;
            if (gtile) {
                ok = true;
            } else if (ct < 17) {
                int j = i0 - 512 + 64 * ct + 2 * jj;
                int d = j - iq;
                ok = (j >= 0) && (j < S_LEN) && (d <= 512) && (d >= -512);
            } else {
                int j = gsh[jj];
                int d = j - iq;
                bool inloc = (d <= 512) && (d >= -512) && ((d & 1) == 0);
                ok = (gval[jj] != 0) && !inloc;
            }
            float p = ok ? __expf(scarr[u] * 0.125f) : 0.f;
            rsum += p;
            Psm[qr][jj] = p;
        }
        __syncthreads();

#pragma unroll 4
        for (int j = 0; j < 32; ++j) {
            float p = Psm[qr][j];
            float4 v1 = *(const float4*)&Vsm[j][4 * sub];
            float4 v2 = *(const float4*)&Vsm[j][32 + 4 * sub];
            acc[0] += p * v1.x; acc[1] += p * v1.y;
            acc[2] += p * v1.z; acc[3] += p * v1.w;
            acc[4] += p * v2.x; acc[5] += p * v2.y;
            acc[6] += p * v2.z; acc[7] += p * v2.w;
        }
    }

    rsum += __shfl_xor_sync(0xffffffffu, rsum, 1);
    rsum += __shfl_xor_sync(0xffffffffu, rsum, 2);
    rsum += __shfl_xor_sync(0xffffffffu, rsum, 4);
    float inv = 1.f / rsum;

    bool wr = gtile || (g_isg[iq] == 0);
    if (wr) {
        float* dst = g_ctx + (b * S_LEN + iq) * D_MODEL + h * HD;
        float4 o1 = make_float4(acc[0] * inv, acc[1] * inv, acc[2] * inv, acc[3] * inv);
        float4 o2 = make_float4(acc[4] * inv, acc[5] * inv, acc[6] * inv, acc[7] * inv);
        *(float4*)&dst[4 * sub] = o1;
        *(float4*)&dst[32 + 4 * sub] = o2;
    }
}

// ---------------------------------------------------------------------------
extern "C" void kernel_launch(void* const* d_in, const int* in_sizes, int n_in,
                              void* d_out, int out_size) {
    const float* q  = (const float*)d_in[0];
    const float* k  = (const float*)d_in[1];
    const float* v  = (const float*)d_in[2];
    const float* Wq = (const float*)d_in[3];
    const float* Wk = (const float*)d_in[4];
    const float* Wv = (const float*)d_in[5];
    const float* Wo = (const float*)d_in[6];
    const float* bq = (const float*)d_in[7];
    const float* bk = (const float*)d_in[8];
    const float* bv = (const float*)d_in[9];
    const float* bo = (const float*)d_in[10];
    const int* gidx = (const int*)d_in[11];
    float* out = (float*)d_out;

    cudaFuncSetAttribute(gemm_mma, cudaFuncAttributeMaxDynamicSharedMemorySize,
                         GEMM_SMEM);

    flags_kernel<<<1, 256>>>(gidx);
    split_main<<<2048, 256>>>(q, k, v, Wq, Wk, Wv, Wo);

    // Fused QKV projection (grid z selects Q/K/V)
    gemm_mma<<<dim3(D_MODEL / 64, SN / 128, 3), 256, GEMM_SMEM>>>(
        -1, nullptr, bq, bk, bv);

    attn_kernel<<<dim3(65, NH, NB), 256>>>(gidx);

    split_ctx<<<1024, 256>>>();
    gemm_mma<<<dim3(D_MODEL / 64, SN / 128, 1), 256, GEMM_SMEM>>>(
        3, out, bo, bo, bo);
}

// round 10
// speedup vs baseline: 2.9605x; 1.7721x over previous
#include <cuda_runtime.h>
#include <cuda_bf16.h>
#include <cstdint>

#define S_LEN 2048
#define D_MODEL 1024
#define NH 16
#define HD 64
#define NB 2
#define NG 32
#define SN (NB * S_LEN)                 // 4096 rows of X
#define XELE (SN * D_MODEL)             // 4,194,304
#define WELE (D_MODEL * D_MODEL)        // 1,048,576
#define TOT_SPLIT (3 * XELE + 4 * WELE) // 16,777,216
#define HELE (NB * NH * S_LEN * HD)     // 4,194,304 per-head-split elements

// ---------------------------------------------------------------------------
// Scratch (device globals: no allocations allowed)
// ---------------------------------------------------------------------------
__device__ float g_ctx[NB * S_LEN * D_MODEL];
__device__ int g_isg[S_LEN];
__device__ int g_gvalid[NG];
// bf16 hi/lo splits of GEMM inputs: [q | k | v | Wq | Wk | Wv | Wo]
__device__ __nv_bfloat16 g_BH[TOT_SPLIT];
__device__ __nv_bfloat16 g_BL[TOT_SPLIT];
// ctx split (for the output projection)
__device__ __nv_bfloat16 g_CH[XELE];
__device__ __nv_bfloat16 g_CL[XELE];
// bf16 hi/lo splits of projected Q/K/V in [B,H,S,HD] (written by QKV GEMM)
__device__ __nv_bfloat16 g_QH[HELE], g_QL[HELE];
__device__ __nv_bfloat16 g_KH[HELE], g_KL[HELE];
__device__ __nv_bfloat16 g_VH[HELE], g_VL[HELE];

// ---------------------------------------------------------------------------
__device__ __forceinline__ uint32_t smem_u32(const void* p) {
    uint32_t a;
    asm("{ .reg .u64 t; cvta.to.shared.u64 t, %1; cvt.u32.u64 %0, t; }"
        : "=r"(a) : "l"(p));
    return a;
}

#define LDM4(R, ADDR) \
    asm volatile("ldmatrix.sync.aligned.m8n8.x4.shared.b16 {%0,%1,%2,%3}, [%4];" \
        : "=r"((R)[0]), "=r"((R)[1]), "=r"((R)[2]), "=r"((R)[3]) : "r"(ADDR))

#define LDM4T(R, ADDR) \
    asm volatile("ldmatrix.sync.aligned.m8n8.x4.trans.shared.b16 {%0,%1,%2,%3}, [%4];" \
        : "=r"((R)[0]), "=r"((R)[1]), "=r"((R)[2]), "=r"((R)[3]) : "r"(ADDR))

#define MMA16816(C, A, B0, B1) \
    asm volatile("mma.sync.aligned.m16n8k16.row.col.f32.bf16.bf16.f32 " \
        "{%0,%1,%2,%3}, {%4,%5,%6,%7}, {%8,%9}, {%0,%1,%2,%3};" \
        : "+f"((C)[0]), "+f"((C)[1]), "+f"((C)[2]), "+f"((C)[3]) \
        : "r"((A)[0]), "r"((A)[1]), "r"((A)[2]), "r"((A)[3]), "r"(B0), "r"(B1))

// ---------------------------------------------------------------------------
// Flags
// ---------------------------------------------------------------------------
__global__ void flags_kernel(const int* __restrict__ gidx) {
    int t = threadIdx.x;
    for (int s = t; s < S_LEN; s += blockDim.x) g_isg[s] = 0;
    __syncthreads();
    if (t < NG) {
        int g = gidx[t];
        g_isg[g] = 1;
        int v = 1;
        for (int w = 0; w < t; ++w)
            if (gidx[w] == g) v = 0;
        g_gvalid[t] = v;
    }
}

// ---------------------------------------------------------------------------
// bf16 hi/lo split helpers
// ---------------------------------------------------------------------------
__device__ __forceinline__ void split4(float4 x, __nv_bfloat16* h, __nv_bfloat16* l) {
    float xs[4] = {x.x, x.y, x.z, x.w};
#pragma unroll
    for (int i = 0; i < 4; ++i) {
        __nv_bfloat16 hi = __float2bfloat16(xs[i]);
        h[i] = hi;
        l[i] = __float2bfloat16(xs[i] - __bfloat162float(hi));
    }
}

__global__ __launch_bounds__(256) void split_main(
    const float* __restrict__ q, const float* __restrict__ k,
    const float* __restrict__ v, const float* __restrict__ wq,
    const float* __restrict__ wk, const float* __restrict__ wv,
    const float* __restrict__ wo)
{
    int n4 = TOT_SPLIT / 4;
    for (int i = blockIdx.x * blockDim.x + threadIdx.x; i < n4;
         i += gridDim.x * blockDim.x) {
        int e = i * 4;
        const float* src;
        if (e < XELE) src = q + e;
        else if (e < 2 * XELE) src = k + (e - XELE);
        else if (e < 3 * XELE) src = v + (e - 2 * XELE);
        else {
            int o = e - 3 * XELE;
            int w = o / WELE;
            int off = o - w * WELE;
            src = ((w == 0) ? wq : (w == 1) ? wk : (w == 2) ? wv : wo) + off;
        }
        float4 x = *(const float4*)src;
        __nv_bfloat16 h[4], l[4];
        split4(x, h, l);
        *(uint2*)&g_BH[e] = *(uint2*)h;
        *(uint2*)&g_BL[e] = *(uint2*)l;
    }
}

__global__ __launch_bounds__(256) void split_ctx() {
    int n4 = XELE / 4;
    for (int i = blockIdx.x * blockDim.x + threadIdx.x; i < n4;
         i += gridDim.x * blockDim.x) {
        int e = i * 4;
        float4 x = *(const float4*)&g_ctx[e];
        __nv_bfloat16 h[4], l[4];
        split4(x, h, l);
        *(uint2*)&g_CH[e] = *(uint2*)h;
        *(uint2*)&g_CL[e] = *(uint2*)l;
    }
}

// ---------------------------------------------------------------------------
// mma.sync GEMM: Y[m,n] = sum_k X[m,k]*W[n,k] + bias[n], fp32 via bf16x3.
// BM=128, BN=64, BK=64. 8 warps, warp tile 32x32. Swizzled smem + ldmatrix.
// mode -1: md = blockIdx.z in {0,1,2} -> write bf16 hi/lo splits of Q/K/V
//          in [B,H,S,HD] (consumed by attn_mma).
// mode  3: X = ctx split, W = Wo split, write fp32 [M,N] to Yout.
// ---------------------------------------------------------------------------
#define STAGE 49152
#define GEMM_SMEM (2 * STAGE)

__global__ __launch_bounds__(256) void gemm_mma(
    int mode, float* __restrict__ Yout,
    const float* __restrict__ b0p, const float* __restrict__ b1p,
    const float* __restrict__ b2p)
{
    extern __shared__ __align__(128) char smc[];
    const uint32_t smem_base = smem_u32(smc);

    int md = (mode < 0) ? (int)blockIdx.z : 3;
    const __nv_bfloat16 *Ah, *Al, *Bh, *Bl;
    const float* bias;
    if (md < 3) {
        Ah = g_BH + (size_t)md * XELE;
        Al = g_BL + (size_t)md * XELE;
        Bh = g_BH + 3 * (size_t)XELE + (size_t)md * WELE;
        Bl = g_BL + 3 * (size_t)XELE + (size_t)md * WELE;
        bias = (md == 0) ? b0p : (md == 1) ? b1p : b2p;
    } else {
        Ah = g_CH; Al = g_CL;
        Bh = g_BH + 3 * (size_t)XELE + 3 * (size_t)WELE;
        Bl = g_BL + 3 * (size_t)XELE + 3 * (size_t)WELE;
        bias = b2p;
    }

    int tid = threadIdx.x;
    int lane = tid & 31, wid = tid >> 5;
    int warp_m = wid & 3, warp_n = wid >> 2;
    int m0 = blockIdx.y * 128, n0 = blockIdx.x * 64;

    int rA = tid >> 1;
    int cA = (tid & 1) * 4;
    int rB = tid >> 2;
    int cB = (tid & 3) * 2;

    const __nv_bfloat16* gAh = Ah + (size_t)(m0 + rA) * D_MODEL;
    const __nv_bfloat16* gAl = Al + (size_t)(m0 + rA) * D_MODEL;
    const __nv_bfloat16* gBh = Bh + (size_t)(n0 + rB) * D_MODEL;
    const __nv_bfloat16* gBl = Bl + (size_t)(n0 + rB) * D_MODEL;

    uint32_t stAo[4], stBo[2];
#pragma unroll
    for (int u = 0; u < 4; ++u)
        stAo[u] = (uint32_t)rA * 128u + (uint32_t)(((cA + u) ^ (rA & 7)) * 16);
#pragma unroll
    for (int u = 0; u < 2; ++u)
        stBo[u] = 32768u + (uint32_t)rB * 128u +
                  (uint32_t)(((cB + u) ^ (rB & 7)) * 16);

    uint32_t aA_off = (uint32_t)(warp_m * 32 + (lane & 15)) * 128u;
    int aA_hi = lane >> 4;
    int lsw = lane & 7;
    uint32_t aB_off = (uint32_t)(warp_n * 32 + ((lane >> 4) << 3) + (lane & 7)) * 128u;
    int aB_hi = (lane >> 3) & 1;

    float acc[2][4][4];
#pragma unroll
    for (int i = 0; i < 2; ++i)
#pragma unroll
        for (int j = 0; j < 4; ++j)
#pragma unroll
            for (int c = 0; c < 4; ++c) acc[i][j][c] = 0.f;

    uint4 va[4], vla[4], vb[2], vlb[2];

#pragma unroll
    for (int u = 0; u < 4; ++u) {
        va[u]  = *(const uint4*)(gAh + (cA + u) * 8);
        vla[u] = *(const uint4*)(gAl + (cA + u) * 8);
    }
#pragma unroll
    for (int u = 0; u < 2; ++u) {
        vb[u]  = *(const uint4*)(gBh + (cB + u) * 8);
        vlb[u] = *(const uint4*)(gBl + (cB + u) * 8);
    }
    {
        char* base = smc;
#pragma unroll
        for (int u = 0; u < 4; ++u) {
            *(uint4*)(base + stAo[u]) = va[u];
            *(uint4*)(base + 16384 + stAo[u]) = vla[u];
        }
#pragma unroll
        for (int u = 0; u < 2; ++u) {
            *(uint4*)(base + stBo[u]) = vb[u];
            *(uint4*)(base + 8192 + stBo[u]) = vlb[u];
        }
    }
    __syncthreads();

    const int NCH = D_MODEL / 64;  // 16
    for (int ci = 0; ci < NCH; ++ci) {
        if (ci < NCH - 1) {
            int kb = (ci + 1) * 64;
#pragma unroll
            for (int u = 0; u < 4; ++u) {
                va[u]  = *(const uint4*)(gAh + kb + (cA + u) * 8);
                vla[u] = *(const uint4*)(gAl + kb + (cA + u) * 8);
            }
#pragma unroll
            for (int u = 0; u < 2; ++u) {
                vb[u]  = *(const uint4*)(gBh + kb + (cB + u) * 8);
                vlb[u] = *(const uint4*)(gBl + kb + (cB + u) * 8);
            }
        }

        uint32_t sb = smem_base + (uint32_t)(ci & 1) * STAGE;
#pragma unroll
        for (int ks = 0; ks < 4; ++ks) {
            uint32_t swA = (uint32_t)(((ks * 2 + aA_hi) ^ lsw) * 16);
            uint32_t swB = (uint32_t)(((ks * 2 + aB_hi) ^ lsw) * 16);
            uint32_t ah[2][4], al_[2][4], bh[2][4], bl_[2][4];
#pragma unroll
            for (int mt = 0; mt < 2; ++mt) {
                LDM4(ah[mt],  sb + aA_off + mt * 2048 + swA);
                LDM4(al_[mt], sb + 16384 + aA_off + mt * 2048 + swA);
            }
#pragma unroll
            for (int nb = 0; nb < 2; ++nb) {
                LDM4(bh[nb],  sb + 32768 + aB_off + nb * 2048 + swB);
                LDM4(bl_[nb], sb + 40960 + aB_off + nb * 2048 + swB);
            }
#pragma unroll
            for (int mt = 0; mt < 2; ++mt) {
#pragma unroll
                for (int nt = 0; nt < 4; ++nt) {
                    int nb = nt >> 1, hp = (nt & 1) * 2;
                    MMA16816(acc[mt][nt], ah[mt], bh[nb][hp], bh[nb][hp + 1]);
                    MMA16816(acc[mt][nt], ah[mt], bl_[nb][hp], bl_[nb][hp + 1]);
                    MMA16816(acc[mt][nt], al_[mt], bh[nb][hp], bh[nb][hp + 1]);
                }
            }
        }

        if (ci < NCH - 1) {
            char* base = smc + ((ci + 1) & 1) * STAGE;
#pragma unroll
            for (int u = 0; u < 4; ++u) {
                *(uint4*)(base + stAo[u]) = va[u];
                *(uint4*)(base + 16384 + stAo[u]) = vla[u];
            }
#pragma unroll
            for (int u = 0; u < 2; ++u) {
                *(uint4*)(base + stBo[u]) = vb[u];
                *(uint4*)(base + 8192 + stBo[u]) = vlb[u];
            }
        }
        __syncthreads();
    }

    // ---- epilogue ----
    int g = lane >> 2, c2 = (lane & 3) * 2;
    __nv_bfloat16 *DH = g_QH, *DL = g_QL;
    if (md == 1) { DH = g_KH; DL = g_KL; }
    else if (md == 2) { DH = g_VH; DL = g_VL; }
#pragma unroll
    for (int mt = 0; mt < 2; ++mt) {
#pragma unroll
        for (int nt = 0; nt < 4; ++nt) {
            int m = m0 + warp_m * 32 + mt * 16 + g;
            int n = n0 + warp_n * 32 + nt * 8 + c2;
            float2 bs = *(const float2*)&bias[n];
            float2 lo = make_float2(acc[mt][nt][0] + bs.x, acc[mt][nt][1] + bs.y);
            float2 hi = make_float2(acc[mt][nt][2] + bs.x, acc[mt][nt][3] + bs.y);
            if (md == 3) {
                *(float2*)&Yout[(size_t)m * D_MODEL + n] = lo;
                *(float2*)&Yout[(size_t)(m + 8) * D_MODEL + n] = hi;
            } else {
                int hh = n >> 6, dd = n & 63;
                int b2a = m >> 11, ssa = m & (S_LEN - 1);
                int b2b = (m + 8) >> 11, ssb = (m + 8) & (S_LEN - 1);
                size_t o1 = (((size_t)b2a * NH + hh) * S_LEN + ssa) * HD + dd;
                size_t o2 = (((size_t)b2b * NH + hh) * S_LEN + ssb) * HD + dd;
                __nv_bfloat16 h0 = __float2bfloat16(lo.x);
                __nv_bfloat16 h1 = __float2bfloat16(lo.y);
                __nv_bfloat16 l0 = __float2bfloat16(lo.x - __bfloat162float(h0));
                __nv_bfloat16 l1 = __float2bfloat16(lo.y - __bfloat162float(h1));
                __nv_bfloat162 ph; ph.x = h0; ph.y = h1;
                __nv_bfloat162 pl; pl.x = l0; pl.y = l1;
                *(__nv_bfloat162*)&DH[o1] = ph;
                *(__nv_bfloat162*)&DL[o1] = pl;
                h0 = __float2bfloat16(hi.x);
                h1 = __float2bfloat16(hi.y);
                l0 = __float2bfloat16(hi.x - __bfloat162float(h0));
                l1 = __float2bfloat16(hi.y - __bfloat162float(h1));
                ph.x = h0; ph.y = h1;
                pl.x = l0; pl.y = l1;
                *(__nv_bfloat162*)&DH[o2] = ph;
                *(__nv_bfloat162*)&DL[o2] = pl;
            }
        }
    }
}

// ---------------------------------------------------------------------------
// Tensor-core attention. Grid (65, NH, NB), 256 threads (8 warps: 2m x 4n).
// bx<64: parity block (32 rows i0+2r); tiles: nloc local 128-col tiles in
//   parity space + 1 global-col tile. bx==64: global-row block, 16 tiles.
// S = Qh*Kh + Qh*Kl + Ql*Kh (mma), P = exp(S/8) masked (fp32, no max-sub),
// P split to bf16 hi/lo in smem, O += Ph*Vh + Ph*Vl + Pl*Vh (mma, V via
// ldmatrix.trans). rsum accumulated in regs, reduced at the end.
// ---------------------------------------------------------------------------
#define OFF_QH 0
#define OFF_QL 4096
#define OFF_KH 8192
#define OFF_KL 24576
#define OFF_VH 40960
#define OFF_VL 57344
#define OFF_PH 73728
#define OFF_PL 81920
#define OFF_RS 90112
#define OFF_INV 90624
#define OFF_GS 90752
#define OFF_GV 90880
#define SMEM_ATTN 91008

__global__ __launch_bounds__(256, 2) void attn_mma(const int* __restrict__ gidx)
{
    extern __shared__ __align__(128) char sm[];
    const uint32_t smb = smem_u32(sm);
    float* rssm = (float*)(sm + OFF_RS);
    float* invsm = (float*)(sm + OFF_INV);
    int* gshs = (int*)(sm + OFF_GS);
    int* gvals = (int*)(sm + OFF_GV);

    int tid = threadIdx.x, lane = tid & 31, wid = tid >> 5;
    int warp_m = wid & 1, warp_n = wid >> 1;
    int b = blockIdx.z, h = blockIdx.y, bx = blockIdx.x;
    bool gt = (bx == 64);
    size_t hb = ((size_t)(b * NH + h)) * S_LEN * HD;

    if (tid < NG) { gshs[tid] = gidx[tid]; gvals[tid] = g_gvalid[tid]; }
    __syncthreads();

    int p = 0, rp0 = 0, i0 = 0, jps = 0, nloc = 0, ntile;
    if (gt) {
        ntile = 16;
    } else {
        p = bx & 1;
        int t2 = bx >> 1;
        rp0 = t2 * 32;
        i0 = t2 * 64 + p;
        jps = rp0 - 256; if (jps < 0) jps = 0;
        int jpe = rp0 + 287; if (jpe > 1023) jpe = 1023;
        nloc = (jpe - jps + 128) >> 7;
        ntile = nloc + 1;
    }

    // Q tile load (32 rows x 64 d, hi+lo)
    {
        int r = tid >> 3, uq = tid & 7;
        int irow = gt ? gshs[r] : (i0 + 2 * r);
        size_t go = hb + (size_t)irow * HD + uq * 8;
        uint32_t doff = (uint32_t)r * 128u + (uint32_t)((uq ^ (r & 7)) << 4);
        *(uint4*)(sm + OFF_QH + doff) = *(const uint4*)(g_QH + go);
        *(uint4*)(sm + OFF_QL + doff) = *(const uint4*)(g_QL + go);
    }

    int g = lane >> 2, c2 = (lane & 3) * 2;
    int r1 = warp_m * 16 + g, r2 = r1 + 8;
    int i1 = gt ? gshs[r1] : (i0 + 2 * r1);
    int i2 = gt ? gshs[r2] : (i0 + 2 * r2);
    int lsw = lane & 7;

    float rs1 = 0.f, rs2 = 0.f;
    float oacc[2][4];
#pragma unroll
    for (int i = 0; i < 2; ++i)
#pragma unroll
        for (int j = 0; j < 4; ++j) oacc[i][j] = 0.f;

    int jslot = tid >> 1, uhalf = (tid & 1) * 4;

    for (int ti = 0; ti < ntile; ++ti) {
        __syncthreads();  // previous tile fully consumed
        // ---- K/V tile load (128 cols x 64 d, 4 arrays) ----
        {
            int s = 0;
            bool valid;
            if (gt) { s = (ti << 7) + jslot; valid = true; }
            else if (ti < nloc) {
                int jp = jps + (ti << 7) + jslot;
                valid = jp < 1024;
                s = 2 * jp + p;
            } else {
                valid = jslot < 32;
                s = valid ? gshs[jslot] : 0;
            }
            size_t ro = hb + (size_t)s * HD;
            const uint4* kh4 = (const uint4*)(g_KH + ro);
            const uint4* kl4 = (const uint4*)(g_KL + ro);
            const uint4* vh4 = (const uint4*)(g_VH + ro);
            const uint4* vl4 = (const uint4*)(g_VL + ro);
            uint4 z = make_uint4(0, 0, 0, 0);
#pragma unroll
            for (int u = 0; u < 4; ++u) {
                int un = uhalf + u;
                uint32_t off = (uint32_t)jslot * 128u +
                               (uint32_t)((un ^ (jslot & 7)) << 4);
                *(uint4*)(sm + OFF_KH + off) = valid ? kh4[un] : z;
                *(uint4*)(sm + OFF_KL + off) = valid ? kl4[un] : z;
                *(uint4*)(sm + OFF_VH + off) = valid ? vh4[un] : z;
                *(uint4*)(sm + OFF_VL + off) = valid ? vl4[un] : z;
            }
        }
        __syncthreads();

        // ---- S = Q*K^T (3-term split) ----
        float sacc[4][4];
#pragma unroll
        for (int i = 0; i < 4; ++i)
#pragma unroll
            for (int j = 0; j < 4; ++j) sacc[i][j] = 0.f;

#pragma unroll
        for (int ks = 0; ks < 4; ++ks) {
            uint32_t qhf[4], qlf[4];
            {
                int rowA = warp_m * 16 + (lane & 15);
                uint32_t addr = smb + OFF_QH + (uint32_t)rowA * 128u +
                                (uint32_t)((((ks * 2 + (lane >> 4)) ^ lsw) & 7) << 4);
                LDM4(qhf, addr);
                LDM4(qlf, addr + (OFF_QL - OFF_QH));
            }
            uint32_t khf[2][4], klf[2][4];
#pragma unroll
            for (int nb = 0; nb < 2; ++nb) {
                int rowB = warp_n * 32 + nb * 16 + ((lane >> 4) << 3) + lsw;
                uint32_t addr = smb + OFF_KH + (uint32_t)rowB * 128u +
                                (uint32_t)((((ks * 2 + ((lane >> 3) & 1)) ^ lsw) & 7) << 4);
                LDM4(khf[nb], addr);
                LDM4(klf[nb], addr + (OFF_KL - OFF_KH));
            }
#pragma unroll
            for (int nt = 0; nt < 4; ++nt) {
                int nb = nt >> 1, hp = (nt & 1) * 2;
                MMA16816(sacc[nt], qhf, khf[nb][hp], khf[nb][hp + 1]);
                MMA16816(sacc[nt], qhf, klf[nb][hp], klf[nb][hp + 1]);
                MMA16816(sacc[nt], qlf, khf[nb][hp], khf[nb][hp + 1]);
            }
        }

        // ---- mask + exp + P split store ----
#pragma unroll
        for (int nt = 0; nt < 4; ++nt) {
            int c0 = warp_n * 32 + nt * 8 + c2;
            bool ok00, ok01, ok10, ok11;
            if (gt) {
                ok00 = ok01 = ok10 = ok11 = true;
            } else if (ti < nloc) {
                int jp0 = jps + (ti << 7) + c0;
                bool j0 = jp0 < 1024, j1 = (jp0 + 1) < 1024;
                int a0 = jp0 - (rp0 + r1);
                int b0_ = jp0 - (rp0 + r2);
                ok00 = j0 && a0 >= -256 && a0 <= 256;
                ok01 = j1 && (a0 + 1) >= -256 && (a0 + 1) <= 256;
                ok10 = j0 && b0_ >= -256 && b0_ <= 256;
                ok11 = j1 && (b0_ + 1) >= -256 && (b0_ + 1) <= 256;
            } else {
                ok00 = ok01 = ok10 = ok11 = false;
                if (c0 < 32) {
                    int s0 = gshs[c0];
                    bool gv = gvals[c0] != 0;
                    int d0 = s0 - i1;
                    ok00 = gv && !(((d0 & 1) == 0) && d0 >= -512 && d0 <= 512);
                    int d2 = s0 - i2;
                    ok10 = gv && !(((d2 & 1) == 0) && d2 >= -512 && d2 <= 512);
                }
                if (c0 + 1 < 32) {
                    int s1 = gshs[c0 + 1];
                    bool gv = gvals[c0 + 1] != 0;
                    int d1 = s1 - i1;
                    ok01 = gv && !(((d1 & 1) == 0) && d1 >= -512 && d1 <= 512);
                    int d3 = s1 - i2;
                    ok11 = gv && !(((d3 & 1) == 0) && d3 >= -512 && d3 <= 512);
                }
            }
            float p00 = ok00 ? __expf(sacc[nt][0] * 0.125f) : 0.f;
            float p01 = ok01 ? __expf(sacc[nt][1] * 0.125f) : 0.f;
            float p10 = ok10 ? __expf(sacc[nt][2] * 0.125f) : 0.f;
            float p11 = ok11 ? __expf(sacc[nt][3] * 0.125f) : 0.f;
            rs1 += p00 + p01;
            rs2 += p10 + p11;

            uint32_t un = (uint32_t)(c0 >> 3);
            uint32_t inb = (uint32_t)((c0 & 7) * 2);
            // row r1
            {
                uint32_t u1 = (un & 8u) | ((un ^ (uint32_t)(r1 & 7)) & 7u);
                uint32_t off = (uint32_t)r1 * 256u + (u1 << 4) + inb;
                __nv_bfloat16 h0 = __float2bfloat16(p00);
                __nv_bfloat16 h1 = __float2bfloat16(p01);
                __nv_bfloat162 ph; ph.x = h0; ph.y = h1;
                __nv_bfloat162 pl;
                pl.x = __float2bfloat16(p00 - __bfloat162float(h0));
                pl.y = __float2bfloat16(p01 - __bfloat162float(h1));
                *(__nv_bfloat162*)(sm + OFF_PH + off) = ph;
                *(__nv_bfloat162*)(sm + OFF_PL + off) = pl;
            }
            // row r2
            {
                uint32_t u1 = (un & 8u) | ((un ^ (uint32_t)(r2 & 7)) & 7u);
                uint32_t off = (uint32_t)r2 * 256u + (u1 << 4) + inb;
                __nv_bfloat16 h0 = __float2bfloat16(p10);
                __nv_bfloat16 h1 = __float2bfloat16(p11);
                __nv_bfloat162 ph; ph.x = h0; ph.y = h1;
                __nv_bfloat162 pl;
                pl.x = __float2bfloat16(p10 - __bfloat162float(h0));
                pl.y = __float2bfloat16(p11 - __bfloat162float(h1));
                *(__nv_bfloat162*)(sm + OFF_PH + off) = ph;
                *(__nv_bfloat162*)(sm + OFF_PL + off) = pl;
            }
        }
        __syncthreads();

        // ---- O += P * V (3-term split, V via ldmatrix.trans) ----
#pragma unroll
        for (int ks = 0; ks < 8; ++ks) {
            uint32_t phf[4], plf[4];
            {
                int rowP = warp_m * 16 + (lane & 15);
                uint32_t un = (uint32_t)(ks * 2 + (lane >> 4));
                uint32_t u1 = (un & 8u) | ((un ^ (uint32_t)(rowP & 7)) & 7u);
                uint32_t addr = smb + OFF_PH + (uint32_t)rowP * 256u + (u1 << 4);
                LDM4(phf, addr);
                LDM4(plf, addr + (OFF_PL - OFF_PH));
            }
            uint32_t vhf[4], vlf[4];
            {
                int rowV = ks * 16 + (lane & 15);
                uint32_t un = (uint32_t)((warp_n * 2 + (lane >> 4)) ^ (rowV & 7));
                uint32_t addr = smb + OFF_VH + (uint32_t)rowV * 128u + (un << 4);
                LDM4T(vhf, addr);
                LDM4T(vlf, addr + (OFF_VL - OFF_VH));
            }
#pragma unroll
            for (int nt2 = 0; nt2 < 2; ++nt2) {
                int hp = nt2 * 2;
                MMA16816(oacc[nt2], phf, vhf[hp], vhf[hp + 1]);
                MMA16816(oacc[nt2], phf, vlf[hp], vlf[hp + 1]);
                MMA16816(oacc[nt2], plf, vhf[hp], vhf[hp + 1]);
            }
        }
    }

    // ---- rsum reduction across quad lanes + warp_n groups ----
    rs1 += __shfl_xor_sync(0xffffffffu, rs1, 1);
    rs1 += __shfl_xor_sync(0xffffffffu, rs1, 2);
    rs2 += __shfl_xor_sync(0xffffffffu, rs2, 1);
    rs2 += __shfl_xor_sync(0xffffffffu, rs2, 2);
    if ((lane & 3) == 0) {
        rssm[warp_n * 32 + r1] = rs1;
        rssm[warp_n * 32 + r2] = rs2;
    }
    __syncthreads();
    if (tid < 32) {
        float t = rssm[tid] + rssm[32 + tid] + rssm[64 + tid] + rssm[96 + tid];
        invsm[tid] = 1.f / t;
    }
    __syncthreads();

    float inv1 = invsm[r1], inv2 = invsm[r2];
    bool w1 = gt || (g_isg[i1] == 0);
    bool w2 = gt || (g_isg[i2] == 0);
#pragma unroll
    for (int nt2 = 0; nt2 < 2; ++nt2) {
        int d = warp_n * 16 + nt2 * 8 + c2;
        if (w1) {
            float2 o = make_float2(oacc[nt2][0] * inv1, oacc[nt2][1] * inv1);
            *(float2*)&g_ctx[((size_t)b * S_LEN + i1) * D_MODEL + h * HD + d] = o;
        }
        if (w2) {
            float2 o = make_float2(oacc[nt2][2] * inv2, oacc[nt2][3] * inv2);
            *(float2*)&g_ctx[((size_t)b * S_LEN + i2) * D_MODEL + h * HD + d] = o;
        }
    }
}

// ---------------------------------------------------------------------------
extern "C" void kernel_launch(void* const* d_in, const int* in_sizes, int n_in,
                              void* d_out, int out_size) {
    const float* q  = (const float*)d_in[0];
    const float* k  = (const float*)d_in[1];
    const float* v  = (const float*)d_in[2];
    const float* Wq = (const float*)d_in[3];
    const float* Wk = (const float*)d_in[4];
    const float* Wv = (const float*)d_in[5];
    const float* Wo = (const float*)d_in[6];
    const float* bq = (const float*)d_in[7];
    const float* bk = (const float*)d_in[8];
    const float* bv = (const float*)d_in[9];
    const float* bo = (const float*)d_in[10];
    const int* gidx = (const int*)d_in[11];
    float* out = (float*)d_out;

    cudaFuncSetAttribute(gemm_mma, cudaFuncAttributeMaxDynamicSharedMemorySize,
                         GEMM_SMEM);
    cudaFuncSetAttribute(attn_mma, cudaFuncAttributeMaxDynamicSharedMemorySize,
                         SMEM_ATTN);

    flags_kernel<<<1, 256>>>(gidx);
    split_main<<<2048, 256>>>(q, k, v, Wq, Wk, Wv, Wo);

    // Fused QKV projection (grid z selects Q/K/V); writes bf16 hi/lo splits.
    gemm_mma<<<dim3(D_MODEL / 64, SN / 128, 3), 256, GEMM_SMEM>>>(
        -1, nullptr, bq, bk, bv);

    attn_mma<<<dim3(65, NH, NB), 256, SMEM_ATTN>>>(gidx);

    split_ctx<<<1024, 256>>>();
    gemm_mma<<<dim3(D_MODEL / 64, SN / 128, 1), 256, GEMM_SMEM>>>(
        3, out, bo, bo, bo);
}

// round 13
// speedup vs baseline: 3.5621x; 1.2032x over previous
#include <cuda_runtime.h>
#include <cuda_bf16.h>
#include <cstdint>

#define S_LEN 2048
#define D_MODEL 1024
#define NH 16
#define HD 64
#define NB 2
#define NG 32
#define SN (NB * S_LEN)                 // 4096 rows of X
#define XELE (SN * D_MODEL)             // 4,194,304
#define WELE (D_MODEL * D_MODEL)        // 1,048,576
#define TOT_SPLIT (3 * XELE + 4 * WELE) // 16,777,216
#define HELE (NB * NH * S_LEN * HD)     // 4,194,304

// ---------------------------------------------------------------------------
// Scratch (device globals: no allocations allowed)
// ---------------------------------------------------------------------------
__device__ float g_ctx[NB * S_LEN * D_MODEL];
__device__ int g_isg[S_LEN];
__device__ int g_gvalid[NG];
// fragment-packed bf16 hi/lo: [q|k|v A-frags (3*XELE) | Wq..Wo B-frags (4*WELE)]
__device__ __nv_bfloat16 g_BH[TOT_SPLIT];
__device__ __nv_bfloat16 g_BL[TOT_SPLIT];
// ctx A-frags (output projection)
__device__ __nv_bfloat16 g_CH[XELE];
__device__ __nv_bfloat16 g_CL[XELE];
// bf16 hi/lo splits of projected Q/K/V in [B,H,S,HD]
__device__ __nv_bfloat16 g_QH[HELE], g_QL[HELE];
__device__ __nv_bfloat16 g_KH[HELE], g_KL[HELE];
__device__ __nv_bfloat16 g_VH[HELE], g_VL[HELE];

// ---------------------------------------------------------------------------
__device__ __forceinline__ uint32_t smem_u32(const void* p) {
    uint32_t a;
    asm("{ .reg .u64 t; cvta.to.shared.u64 t, %1; cvt.u32.u64 %0, t; }"
        : "=r"(a) : "l"(p));
    return a;
}

#define LDM4(R, ADDR) \
    asm volatile("ldmatrix.sync.aligned.m8n8.x4.shared.b16 {%0,%1,%2,%3}, [%4];" \
        : "=r"((R)[0]), "=r"((R)[1]), "=r"((R)[2]), "=r"((R)[3]) : "r"(ADDR))

#define LDM4T(R, ADDR) \
    asm volatile("ldmatrix.sync.aligned.m8n8.x4.trans.shared.b16 {%0,%1,%2,%3}, [%4];" \
        : "=r"((R)[0]), "=r"((R)[1]), "=r"((R)[2]), "=r"((R)[3]) : "r"(ADDR))

#define MMA16816(C, A, B0, B1) \
    asm volatile("mma.sync.aligned.m16n8k16.row.col.f32.bf16.bf16.f32 " \
        "{%0,%1,%2,%3}, {%4,%5,%6,%7}, {%8,%9}, {%0,%1,%2,%3};" \
        : "+f"((C)[0]), "+f"((C)[1]), "+f"((C)[2]), "+f"((C)[3]) \
        : "r"((A)[0]), "r"((A)[1]), "r"((A)[2]), "r"((A)[3]), "r"(B0), "r"(B1))

#define MMA16816_V(C, A0, A1, A2, A3, B0, B1) \
    asm volatile("mma.sync.aligned.m16n8k16.row.col.f32.bf16.bf16.f32 " \
        "{%0,%1,%2,%3}, {%4,%5,%6,%7}, {%8,%9}, {%0,%1,%2,%3};" \
        : "+f"((C)[0]), "+f"((C)[1]), "+f"((C)[2]), "+f"((C)[3]) \
        : "r"(A0), "r"(A1), "r"(A2), "r"(A3), "r"(B0), "r"(B1))

// ---------------------------------------------------------------------------
// Flags
// ---------------------------------------------------------------------------
__global__ void flags_kernel(const int* __restrict__ gidx) {
    int t = threadIdx.x;
    for (int s = t; s < S_LEN; s += blockDim.x) g_isg[s] = 0;
    __syncthreads();
    if (t < NG) {
        int g = gidx[t];
        g_isg[g] = 1;
        int v = 1;
        for (int w = 0; w < t; ++w)
            if (gidx[w] == g) v = 0;
        g_gvalid[t] = v;
    }
}

// ---------------------------------------------------------------------------
// Fragment packing.
// A-frag (16x16, row-major, mma a0..a3 pair layout): lane = g*4+qd
//   reg0={(g,c2),(g,c2+1)}, reg1={(g+8,c2),(g+8,c2+1)},
//   reg2={(g,c2+8),(g,c2+9)}, reg3={(g+8,c2+8),(g+8,c2+9)}; c2=qd*2
//   frag id f = (rt*64 + kt)*4 + mt; 256 bf16/frag; lane offset lane*8.
// B-frag pair (two k16 steps, col-major B = W[n][k]): lane = g*4+qd
//   reg0={W[n=g][c2],W[g][c2+1]}, reg1={W[g][c2+8],W[g][c2+9]}  (kt even)
//   reg2/reg3 same at k+16 (kt odd); f = nt8*32 + ktp; 256 bf16/frag-pair.
// ---------------------------------------------------------------------------
__device__ __forceinline__ uint32_t pack_pair(float a, float b,
                                              uint32_t& lo_out) {
    __nv_bfloat16 ha = __float2bfloat16(a);
    __nv_bfloat16 hb = __float2bfloat16(b);
    __nv_bfloat16 la = __float2bfloat16(a - __bfloat162float(ha));
    __nv_bfloat16 lb = __float2bfloat16(b - __bfloat162float(hb));
    uint32_t hi = ((uint32_t)*(uint16_t*)&hb << 16) | *(uint16_t*)&ha;
    lo_out = ((uint32_t)*(uint16_t*)&lb << 16) | *(uint16_t*)&la;
    return hi;
}

__global__ __launch_bounds__(256) void pack_all(
    const float* __restrict__ q, const float* __restrict__ k,
    const float* __restrict__ v, const float* __restrict__ wq,
    const float* __restrict__ wk, const float* __restrict__ wv,
    const float* __restrict__ wo)
{
    int gf = blockIdx.x * 8 + (threadIdx.x >> 5);
    int lane = threadIdx.x & 31;
    int g = lane >> 2, qd = lane & 3;
    uint32_t hi[4], lo[4];
    size_t dst;
    if (gf < 49152) {  // A-type frags: 3 modes x 16384
        int mode = gf >> 14;
        int f = gf & 16383;
        int mt = f & 3, kt = (f >> 2) & 63, rt = f >> 8;
        const float* X = (mode == 0) ? q : (mode == 1) ? k : v;
        int row0 = rt * 64 + mt * 16 + g;
        int k0 = kt * 16 + qd * 2;
        const float* r0 = X + (size_t)row0 * D_MODEL + k0;
        const float* r8 = r0 + 8 * D_MODEL;
        hi[0] = pack_pair(r0[0], r0[1], lo[0]);
        hi[1] = pack_pair(r8[0], r8[1], lo[1]);
        hi[2] = pack_pair(r0[8], r0[9], lo[2]);
        hi[3] = pack_pair(r8[8], r8[9], lo[3]);
        dst = (size_t)mode * XELE + (size_t)f * 256 + lane * 8;
    } else {           // B-type frags: 4 weights x 4096
        int bf = gf - 49152;
        int w = bf >> 12;
        int f = bf & 4095;
        int nt8 = f >> 5, ktp = f & 31;
        const float* W = (w == 0) ? wq : (w == 1) ? wk : (w == 2) ? wv : wo;
        const float* r = W + (size_t)(nt8 * 8 + g) * D_MODEL + ktp * 32 + qd * 2;
        hi[0] = pack_pair(r[0], r[1], lo[0]);
        hi[1] = pack_pair(r[8], r[9], lo[1]);
        hi[2] = pack_pair(r[16], r[17], lo[2]);
        hi[3] = pack_pair(r[24], r[25], lo[3]);
        dst = 3 * (size_t)XELE + (size_t)w * WELE + (size_t)f * 256 + lane * 8;
    }
    *(uint4*)(g_BH + dst) = make_uint4(hi[0], hi[1], hi[2], hi[3]);
    *(uint4*)(g_BL + dst) = make_uint4(lo[0], lo[1], lo[2], lo[3]);
}

__global__ __launch_bounds__(256) void pack_ctx() {
    int f = blockIdx.x * 8 + (threadIdx.x >> 5);  // 16384 frags
    int lane = threadIdx.x & 31;
    int g = lane >> 2, qd = lane & 3;
    int mt = f & 3, kt = (f >> 2) & 63, rt = f >> 8;
    int row0 = rt * 64 + mt * 16 + g;
    int k0 = kt * 16 + qd * 2;
    const float* r0 = g_ctx + (size_t)row0 * D_MODEL + k0;
    const float* r8 = r0 + 8 * D_MODEL;
    uint32_t hi[4], lo[4];
    hi[0] = pack_pair(r0[0], r0[1], lo[0]);
    hi[1] = pack_pair(r8[0], r8[1], lo[1]);
    hi[2] = pack_pair(r0[8], r0[9], lo[2]);
    hi[3] = pack_pair(r8[8], r8[9], lo[3]);
    size_t dst = (size_t)f * 256 + lane * 8;
    *(uint4*)(g_CH + dst) = make_uint4(hi[0], hi[1], hi[2], hi[3]);
    *(uint4*)(g_CL + dst) = make_uint4(lo[0], lo[1], lo[2], lo[3]);
}

// ---------------------------------------------------------------------------
// Fragment GEMM: no smem, LDG.128 directly into mma fragments.
// Block 128x128, 8 warps (2m x 4n), warp tile 64x32. K loop in k32 pairs.
// mode -1: md = blockIdx.z in {0,1,2} -> bf16 hi/lo splits of Q/K/V.
// mode  3: A = ctx frags, B = Wo frags, fp32 [M,N] to Yout.
// ---------------------------------------------------------------------------
__global__ __launch_bounds__(256, 1) void gemm_frag(
    int mode, float* __restrict__ Yout,
    const float* __restrict__ b0p, const float* __restrict__ b1p,
    const float* __restrict__ b2p)
{
    int md = (mode < 0) ? (int)blockIdx.z : 3;
    const __nv_bfloat16 *AHp, *ALp;
    const float* bias;
    if (md < 3) {
        AHp = g_BH + (size_t)md * XELE;
        ALp = g_BL + (size_t)md * XELE;
        bias = (md == 0) ? b0p : (md == 1) ? b1p : b2p;
    } else {
        AHp = g_CH; ALp = g_CL; bias = b2p;
    }
    int wsel = (md == 3) ? 3 : md;
    const __nv_bfloat16* BHp = g_BH + 3 * (size_t)XELE + (size_t)wsel * WELE;
    const __nv_bfloat16* BLp = g_BL + 3 * (size_t)XELE + (size_t)wsel * WELE;

    int tid = threadIdx.x, lane = tid & 31, wid = tid >> 5;
    int warp_m = wid & 1, warp_n = wid >> 1;
    int m0 = blockIdx.y * 128, n0 = blockIdx.x * 128;
    int rt0 = (m0 >> 6) + warp_m;
    int nt80 = (n0 >> 3) + warp_n * 4;

    const uint4* aH = (const uint4*)AHp + (size_t)rt0 * 8192 + lane;
    const uint4* aL = (const uint4*)ALp + (size_t)rt0 * 8192 + lane;
    const uint4* bH = (const uint4*)BHp + (size_t)nt80 * 1024 + lane;
    const uint4* bL = (const uint4*)BLp + (size_t)nt80 * 1024 + lane;

    float acc[4][4][4];
#pragma unroll
    for (int i = 0; i < 4; ++i)
#pragma unroll
        for (int j = 0; j < 4; ++j)
#pragma unroll
            for (int c = 0; c < 4; ++c) acc[i][j][c] = 0.f;

    for (int ktp = 0; ktp < 32; ++ktp) {
        uint4 fah[4][2], fal[4][2], fbh[4], fbl[4];
#pragma unroll
        for (int mt = 0; mt < 4; ++mt)
#pragma unroll
            for (int kk = 0; kk < 2; ++kk) {
                int kt = ktp * 2 + kk;
                fah[mt][kk] = aH[(kt * 4 + mt) * 32];
                fal[mt][kk] = aL[(kt * 4 + mt) * 32];
            }
#pragma unroll
        for (int nb = 0; nb < 4; ++nb) {
            fbh[nb] = bH[(nb * 32 + ktp) * 32];
            fbl[nb] = bL[(nb * 32 + ktp) * 32];
        }
#pragma unroll
        for (int kk = 0; kk < 2; ++kk) {
#pragma unroll
            for (int mt = 0; mt < 4; ++mt) {
                uint32_t ah0 = fah[mt][kk].x, ah1 = fah[mt][kk].y,
                         ah2 = fah[mt][kk].z, ah3 = fah[mt][kk].w;
                uint32_t al0 = fal[mt][kk].x, al1 = fal[mt][kk].y,
                         al2 = fal[mt][kk].z, al3 = fal[mt][kk].w;
#pragma unroll
                for (int nb = 0; nb < 4; ++nb) {
                    uint32_t b0 = kk ? fbh[nb].z : fbh[nb].x;
                    uint32_t b1 = kk ? fbh[nb].w : fbh[nb].y;
                    uint32_t c0 = kk ? fbl[nb].z : fbl[nb].x;
                    uint32_t c1 = kk ? fbl[nb].w : fbl[nb].y;
                    MMA16816_V(acc[mt][nb], ah0, ah1, ah2, ah3, b0, b1);
                    MMA16816_V(acc[mt][nb], ah0, ah1, ah2, ah3, c0, c1);
                    MMA16816_V(acc[mt][nb], al0, al1, al2, al3, b0, b1);
                }
            }
        }
    }

    // ---- epilogue ----
    int g = lane >> 2, c2 = (lane & 3) * 2;
#pragma unroll
    for (int mt = 0; mt < 4; ++mt) {
#pragma unroll
        for (int nb = 0; nb < 4; ++nb) {
            int m = m0 + warp_m * 64 + mt * 16 + g;
            int n = n0 + warp_n * 32 + nb * 8 + c2;
            float2 bs = *(const float2*)&bias[n];
            float2 lo = make_float2(acc[mt][nb][0] + bs.x, acc[mt][nb][1] + bs.y);
            float2 hi = make_float2(acc[mt][nb][2] + bs.x, acc[mt][nb][3] + bs.y);
            if (md == 3) {
                *(float2*)&Yout[(size_t)m * D_MODEL + n] = lo;
                *(float2*)&Yout[(size_t)(m + 8) * D_MODEL + n] = hi;
            } else {
                __nv_bfloat16* DH = (md == 0) ? g_QH : (md == 1) ? g_KH : g_VH;
                __nv_bfloat16* DL = (md == 0) ? g_QL : (md == 1) ? g_KL : g_VL;
                int hh = n >> 6, dd = n & 63;
                int b2a = m >> 11, ssa = m & (S_LEN - 1);
                int b2b = (m + 8) >> 11, ssb = (m + 8) & (S_LEN - 1);
                size_t o1 = (((size_t)b2a * NH + hh) * S_LEN + ssa) * HD + dd;
                size_t o2 = (((size_t)b2b * NH + hh) * S_LEN + ssb) * HD + dd;
                uint32_t plo, phi;
                phi = pack_pair(lo.x, lo.y, plo);
                *(uint32_t*)&DH[o1] = phi;
                *(uint32_t*)&DL[o1] = plo;
                phi = pack_pair(hi.x, hi.y, plo);
                *(uint32_t*)&DH[o2] = phi;
                *(uint32_t*)&DL[o2] = plo;
            }
        }
    }
}

// ---------------------------------------------------------------------------
// Tensor-core attention (R9 structure + global-col-tile work skipping).
// ---------------------------------------------------------------------------
#define OFF_QH 0
#define OFF_QL 4096
#define OFF_KH 8192
#define OFF_KL 24576
#define OFF_VH 40960
#define OFF_VL 57344
#define OFF_PH 73728
#define OFF_PL 81920
#define OFF_RS 90112
#define OFF_INV 90624
#define OFF_GS 90752
#define OFF_GV 90880
#define SMEM_ATTN 91008

__global__ __launch_bounds__(256, 2) void attn_mma(const int* __restrict__ gidx)
{
    extern __shared__ __align__(128) char sm[];
    const uint32_t smb = smem_u32(sm);
    float* rssm = (float*)(sm + OFF_RS);
    float* invsm = (float*)(sm + OFF_INV);
    int* gshs = (int*)(sm + OFF_GS);
    int* gvals = (int*)(sm + OFF_GV);

    int tid = threadIdx.x, lane = tid & 31, wid = tid >> 5;
    int warp_m = wid & 1, warp_n = wid >> 1;
    int b = blockIdx.z, h = blockIdx.y, bx = blockIdx.x;
    bool gt = (bx == 64);
    size_t hb = ((size_t)(b * NH + h)) * S_LEN * HD;

    if (tid < NG) { gshs[tid] = gidx[tid]; gvals[tid] = g_gvalid[tid]; }
    __syncthreads();

    int p = 0, rp0 = 0, i0 = 0, jps = 0, nloc = 0, ntile;
    if (gt) {
        ntile = 16;
    } else {
        p = bx & 1;
        int t2 = bx >> 1;
        rp0 = t2 * 32;
        i0 = t2 * 64 + p;
        jps = rp0 - 256; if (jps < 0) jps = 0;
        int jpe = rp0 + 287; if (jpe > 1023) jpe = 1023;
        nloc = (jpe - jps + 128) >> 7;
        ntile = nloc + 1;
    }

    // Q tile load (32 rows x 64 d, hi+lo)
    {
        int r = tid >> 3, uq = tid & 7;
        int irow = gt ? gshs[r] : (i0 + 2 * r);
        size_t go = hb + (size_t)irow * HD + uq * 8;
        uint32_t doff = (uint32_t)r * 128u + (uint32_t)((uq ^ (r & 7)) << 4);
        *(uint4*)(sm + OFF_QH + doff) = *(const uint4*)(g_QH + go);
        *(uint4*)(sm + OFF_QL + doff) = *(const uint4*)(g_QL + go);
    }

    int g = lane >> 2, c2 = (lane & 3) * 2;
    int r1 = warp_m * 16 + g, r2 = r1 + 8;
    int i1 = gt ? gshs[r1] : (i0 + 2 * r1);
    int i2 = gt ? gshs[r2] : (i0 + 2 * r2);
    int lsw = lane & 7;

    float rs1 = 0.f, rs2 = 0.f;
    float oacc[2][4];
#pragma unroll
    for (int i = 0; i < 2; ++i)
#pragma unroll
        for (int j = 0; j < 4; ++j) oacc[i][j] = 0.f;

    int jslot = tid >> 1, uhalf = (tid & 1) * 4;

    for (int ti = 0; ti < ntile; ++ti) {
        bool gcol = (!gt) && (ti == nloc);
        __syncthreads();  // previous tile fully consumed
        // ---- K/V tile load ----
        {
            int s = 0;
            bool valid;
            if (gt) { s = (ti << 7) + jslot; valid = true; }
            else if (ti < nloc) {
                int jp = jps + (ti << 7) + jslot;
                valid = jp < 1024;
                s = 2 * jp + p;
            } else {
                valid = jslot < 32;
                s = valid ? gshs[jslot] : 0;
            }
            if (valid || !gcol) {  // gcol tile: rows >=32 never read
                size_t ro = hb + (size_t)s * HD;
                const uint4* kh4 = (const uint4*)(g_KH + ro);
                const uint4* kl4 = (const uint4*)(g_KL + ro);
                const uint4* vh4 = (const uint4*)(g_VH + ro);
                const uint4* vl4 = (const uint4*)(g_VL + ro);
                uint4 z = make_uint4(0, 0, 0, 0);
#pragma unroll
                for (int u = 0; u < 4; ++u) {
                    int un = uhalf + u;
                    uint32_t off = (uint32_t)jslot * 128u +
                                   (uint32_t)((un ^ (jslot & 7)) << 4);
                    *(uint4*)(sm + OFF_KH + off) = valid ? kh4[un] : z;
                    *(uint4*)(sm + OFF_KL + off) = valid ? kl4[un] : z;
                    *(uint4*)(sm + OFF_VH + off) = valid ? vh4[un] : z;
                    *(uint4*)(sm + OFF_VL + off) = valid ? vl4[un] : z;
                }
            }
        }
        __syncthreads();

        // ---- S = Q*K^T (3-term split) ----
        float sacc[4][4];
#pragma unroll
        for (int i = 0; i < 4; ++i)
#pragma unroll
            for (int j = 0; j < 4; ++j) sacc[i][j] = 0.f;

        if (!(gcol && warp_n > 0)) {  // gcol: only warp_n==0 has live cols
#pragma unroll
            for (int ks = 0; ks < 4; ++ks) {
                uint32_t qhf[4], qlf[4];
                {
                    int rowA = warp_m * 16 + (lane & 15);
                    uint32_t addr = smb + OFF_QH + (uint32_t)rowA * 128u +
                                    (uint32_t)((((ks * 2 + (lane >> 4)) ^ lsw) & 7) << 4);
                    LDM4(qhf, addr);
                    LDM4(qlf, addr + (OFF_QL - OFF_QH));
                }
                uint32_t khf[2][4], klf[2][4];
#pragma unroll
                for (int nb = 0; nb < 2; ++nb) {
                    int rowB = warp_n * 32 + nb * 16 + ((lane >> 4) << 3) + lsw;
                    uint32_t addr = smb + OFF_KH + (uint32_t)rowB * 128u +
                                    (uint32_t)((((ks * 2 + ((lane >> 3) & 1)) ^ lsw) & 7) << 4);
                    LDM4(khf[nb], addr);
                    LDM4(klf[nb], addr + (OFF_KL - OFF_KH));
                }
#pragma unroll
                for (int nt = 0; nt < 4; ++nt) {
                    int nb = nt >> 1, hp = (nt & 1) * 2;
                    MMA16816(sacc[nt], qhf, khf[nb][hp], khf[nb][hp + 1]);
                    MMA16816(sacc[nt], qhf, klf[nb][hp], klf[nb][hp + 1]);
                    MMA16816(sacc[nt], qlf, khf[nb][hp], khf[nb][hp + 1]);
                }
            }
        }

        // ---- mask + exp + P split store ----
#pragma unroll
        for (int nt = 0; nt < 4; ++nt) {
            int c0 = warp_n * 32 + nt * 8 + c2;
            bool ok00, ok01, ok10, ok11;
            if (gt) {
                ok00 = ok01 = ok10 = ok11 = true;
            } else if (ti < nloc) {
                int jp0 = jps + (ti << 7) + c0;
                bool j0 = jp0 < 1024, j1 = (jp0 + 1) < 1024;
                int a0 = jp0 - (rp0 + r1);
                int b0_ = jp0 - (rp0 + r2);
                ok00 = j0 && a0 >= -256 && a0 <= 256;
                ok01 = j1 && (a0 + 1) >= -256 && (a0 + 1) <= 256;
                ok10 = j0 && b0_ >= -256 && b0_ <= 256;
                ok11 = j1 && (b0_ + 1) >= -256 && (b0_ + 1) <= 256;
            } else {
                ok00 = ok01 = ok10 = ok11 = false;
                if (c0 < 32) {
                    int s0 = gshs[c0];
                    bool gv = gvals[c0] != 0;
                    int d0 = s0 - i1;
                    ok00 = gv && !(((d0 & 1) == 0) && d0 >= -512 && d0 <= 512);
                    int d2 = s0 - i2;
                    ok10 = gv && !(((d2 & 1) == 0) && d2 >= -512 && d2 <= 512);
                }
                if (c0 + 1 < 32) {
                    int s1 = gshs[c0 + 1];
                    bool gv = gvals[c0 + 1] != 0;
                    int d1 = s1 - i1;
                    ok01 = gv && !(((d1 & 1) == 0) && d1 >= -512 && d1 <= 512);
                    int d3 = s1 - i2;
                    ok11 = gv && !(((d3 & 1) == 0) && d3 >= -512 && d3 <= 512);
                }
            }
            float p00 = ok00 ? __expf(sacc[nt][0] * 0.125f) : 0.f;
            float p01 = ok01 ? __expf(sacc[nt][1] * 0.125f) : 0.f;
            float p10 = ok10 ? __expf(sacc[nt][2] * 0.125f) : 0.f;
            float p11 = ok11 ? __expf(sacc[nt][3] * 0.125f) : 0.f;
            rs1 += p00 + p01;
            rs2 += p10 + p11;

            uint32_t un = (uint32_t)(c0 >> 3);
            uint32_t inb = (uint32_t)((c0 & 7) * 2);
            {
                uint32_t u1 = (un & 8u) | ((un ^ (uint32_t)(r1 & 7)) & 7u);
                uint32_t off = (uint32_t)r1 * 256u + (u1 << 4) + inb;
                uint32_t plo, phi;
                phi = pack_pair(p00, p01, plo);
                *(uint32_t*)(sm + OFF_PH + off) = phi;
                *(uint32_t*)(sm + OFF_PL + off) = plo;
            }
            {
                uint32_t u1 = (un & 8u) | ((un ^ (uint32_t)(r2 & 7)) & 7u);
                uint32_t off = (uint32_t)r2 * 256u + (u1 << 4) + inb;
                uint32_t plo, phi;
                phi = pack_pair(p10, p11, plo);
                *(uint32_t*)(sm + OFF_PH + off) = phi;
                *(uint32_t*)(sm + OFF_PL + off) = plo;
            }
        }
        __syncthreads();

        // ---- O += P * V (3-term split, V via ldmatrix.trans) ----
        int ksN = gcol ? 2 : 8;  // gcol tile: only j<32 contribute
        for (int ks = 0; ks < ksN; ++ks) {
            uint32_t phf[4], plf[4];
            {
                int rowP = warp_m * 16 + (lane & 15);
                uint32_t un = (uint32_t)(ks * 2 + (lane >> 4));
                uint32_t u1 = (un & 8u) | ((un ^ (uint32_t)(rowP & 7)) & 7u);
                uint32_t addr = smb + OFF_PH + (uint32_t)rowP * 256u + (u1 << 4);
                LDM4(phf, addr);
                LDM4(plf, addr + (OFF_PL - OFF_PH));
            }
            uint32_t vhf[4], vlf[4];
            {
                int rowV = ks * 16 + (lane & 15);
                uint32_t un = (uint32_t)((warp_n * 2 + (lane >> 4)) ^ (rowV & 7));
                uint32_t addr = smb + OFF_VH + (uint32_t)rowV * 128u + (un << 4);
                LDM4T(vhf, addr);
                LDM4T(vlf, addr + (OFF_VL - OFF_VH));
            }
#pragma unroll
            for (int nt2 = 0; nt2 < 2; ++nt2) {
                int hp = nt2 * 2;
                MMA16816(oacc[nt2], phf, vhf[hp], vhf[hp + 1]);
                MMA16816(oacc[nt2], phf, vlf[hp], vlf[hp + 1]);
                MMA16816(oacc[nt2], plf, vhf[hp], vhf[hp + 1]);
            }
        }
    }

    // ---- rsum reduction ----
    rs1 += __shfl_xor_sync(0xffffffffu, rs1, 1);
    rs1 += __shfl_xor_sync(0xffffffffu, rs1, 2);
    rs2 += __shfl_xor_sync(0xffffffffu, rs2, 1);
    rs2 += __shfl_xor_sync(0xffffffffu, rs2, 2);
    if ((lane & 3) == 0) {
        rssm[warp_n * 32 + r1] = rs1;
        rssm[warp_n * 32 + r2] = rs2;
    }
    __syncthreads();
    if (tid < 32) {
        float t = rssm[tid] + rssm[32 + tid] + rssm[64 + tid] + rssm[96 + tid];
        invsm[tid] = 1.f / t;
    }
    __syncthreads();

    float inv1 = invsm[r1], inv2 = invsm[r2];
    bool w1 = gt || (g_isg[i1] == 0);
    bool w2 = gt || (g_isg[i2] == 0);
#pragma unroll
    for (int nt2 = 0; nt2 < 2; ++nt2) {
        int d = warp_n * 16 + nt2 * 8 + c2;
        if (w1) {
            float2 o = make_float2(oacc[nt2][0] * inv1, oacc[nt2][1] * inv1);
            *(float2*)&g_ctx[((size_t)b * S_LEN + i1) * D_MODEL + h * HD + d] = o;
        }
        if (w2) {
            float2 o = make_float2(oacc[nt2][2] * inv2, oacc[nt2][3] * inv2);
            *(float2*)&g_ctx[((size_t)b * S_LEN + i2) * D_MODEL + h * HD + d] = o;
        }
    }
}

// ---------------------------------------------------------------------------
extern "C" void kernel_launch(void* const* d_in, const int* in_sizes, int n_in,
                              void* d_out, int out_size) {
    const float* q  = (const float*)d_in[0];
    const float* k  = (const float*)d_in[1];
    const float* v  = (const float*)d_in[2];
    const float* Wq = (const float*)d_in[3];
    const float* Wk = (const float*)d_in[4];
    const float* Wv = (const float*)d_in[5];
    const float* Wo = (const float*)d_in[6];
    const float* bq = (const float*)d_in[7];
    const float* bk = (const float*)d_in[8];
    const float* bv = (const float*)d_in[9];
    const float* bo = (const float*)d_in[10];
    const int* gidx = (const int*)d_in[11];
    float* out = (float*)d_out;

    cudaFuncSetAttribute(attn_mma, cudaFuncAttributeMaxDynamicSharedMemorySize,
                         SMEM_ATTN);

    flags_kernel<<<1, 256>>>(gidx);
    pack_all<<<8192, 256>>>(q, k, v, Wq, Wk, Wv, Wo);

    // Fused QKV projection (grid z selects Q/K/V); writes bf16 hi/lo splits.
    gemm_frag<<<dim3(D_MODEL / 128, SN / 128, 3), 256>>>(-1, nullptr, bq, bk, bv);

    attn_mma<<<dim3(65, NH, NB), 256, SMEM_ATTN>>>(gidx);

    pack_ctx<<<2048, 256>>>();
    gemm_frag<<<dim3(D_MODEL / 128, SN / 128, 1), 256>>>(3, out, bo, bo, bo);
}

// round 15
// speedup vs baseline: 3.8672x; 1.0856x over previous
#include <cuda_runtime.h>
#include <cuda_bf16.h>
#include <cstdint>

#define S_LEN 2048
#define D_MODEL 1024
#define NH 16
#define HD 64
#define NB 2
#define NG 32
#define SN (NB * S_LEN)                 // 4096 rows of X
#define XELE (SN * D_MODEL)             // 4,194,304
#define WELE (D_MODEL * D_MODEL)        // 1,048,576
#define TOT_SPLIT (3 * XELE + 4 * WELE) // 16,777,216
#define HELE (NB * NH * S_LEN * HD)     // 4,194,304

// ---------------------------------------------------------------------------
// Scratch (device globals: no allocations allowed)
// ---------------------------------------------------------------------------
__device__ int g_isg[S_LEN];
__device__ int g_gvalid[NG];
// fragment-packed bf16 hi/lo: [q|k|v A-frags (3*XELE) | Wq..Wo B-frags (4*WELE)]
__device__ __nv_bfloat16 g_BH[TOT_SPLIT];
__device__ __nv_bfloat16 g_BL[TOT_SPLIT];
// ctx A-frags (written directly by attn epilogue; read by output projection)
__device__ __nv_bfloat16 g_CH[XELE];
__device__ __nv_bfloat16 g_CL[XELE];
// bf16 hi/lo splits of projected Q/K/V in [B,H,S,HD]
__device__ __nv_bfloat16 g_QH[HELE], g_QL[HELE];
__device__ __nv_bfloat16 g_KH[HELE], g_KL[HELE];
__device__ __nv_bfloat16 g_VH[HELE], g_VL[HELE];

// ---------------------------------------------------------------------------
__device__ __forceinline__ uint32_t smem_u32(const void* p) {
    uint32_t a;
    asm("{ .reg .u64 t; cvta.to.shared.u64 t, %1; cvt.u32.u64 %0, t; }"
        : "=r"(a) : "l"(p));
    return a;
}

#define LDM4(R, ADDR) \
    asm volatile("ldmatrix.sync.aligned.m8n8.x4.shared.b16 {%0,%1,%2,%3}, [%4];" \
        : "=r"((R)[0]), "=r"((R)[1]), "=r"((R)[2]), "=r"((R)[3]) : "r"(ADDR))

#define LDM4T(R, ADDR) \
    asm volatile("ldmatrix.sync.aligned.m8n8.x4.trans.shared.b16 {%0,%1,%2,%3}, [%4];" \
        : "=r"((R)[0]), "=r"((R)[1]), "=r"((R)[2]), "=r"((R)[3]) : "r"(ADDR))

#define MMA16816(C, A, B0, B1) \
    asm volatile("mma.sync.aligned.m16n8k16.row.col.f32.bf16.bf16.f32 " \
        "{%0,%1,%2,%3}, {%4,%5,%6,%7}, {%8,%9}, {%0,%1,%2,%3};" \
        : "+f"((C)[0]), "+f"((C)[1]), "+f"((C)[2]), "+f"((C)[3]) \
        : "r"((A)[0]), "r"((A)[1]), "r"((A)[2]), "r"((A)[3]), "r"(B0), "r"(B1))

#define MMA16816_V(C, A0, A1, A2, A3, B0, B1) \
    asm volatile("mma.sync.aligned.m16n8k16.row.col.f32.bf16.bf16.f32 " \
        "{%0,%1,%2,%3}, {%4,%5,%6,%7}, {%8,%9}, {%0,%1,%2,%3};" \
        : "+f"((C)[0]), "+f"((C)[1]), "+f"((C)[2]), "+f"((C)[3]) \
        : "r"(A0), "r"(A1), "r"(A2), "r"(A3), "r"(B0), "r"(B1))

// ---------------------------------------------------------------------------
// Flags
// ---------------------------------------------------------------------------
__global__ void flags_kernel(const int* __restrict__ gidx) {
    int t = threadIdx.x;
    for (int s = t; s < S_LEN; s += blockDim.x) g_isg[s] = 0;
    __syncthreads();
    if (t < NG) {
        int g = gidx[t];
        g_isg[g] = 1;
        int v = 1;
        for (int w = 0; w < t; ++w)
            if (gidx[w] == g) v = 0;
        g_gvalid[t] = v;
    }
}

// ---------------------------------------------------------------------------
// Fragment packing (layouts documented in R10; unchanged).
// ---------------------------------------------------------------------------
__device__ __forceinline__ uint32_t pack_pair(float a, float b,
                                              uint32_t& lo_out) {
    __nv_bfloat16 ha = __float2bfloat16(a);
    __nv_bfloat16 hb = __float2bfloat16(b);
    __nv_bfloat16 la = __float2bfloat16(a - __bfloat162float(ha));
    __nv_bfloat16 lb = __float2bfloat16(b - __bfloat162float(hb));
    uint32_t hi = ((uint32_t)*(uint16_t*)&hb << 16) | *(uint16_t*)&ha;
    lo_out = ((uint32_t)*(uint16_t*)&lb << 16) | *(uint16_t*)&la;
    return hi;
}

__global__ __launch_bounds__(256) void pack_all(
    const float* __restrict__ q, const float* __restrict__ k,
    const float* __restrict__ v, const float* __restrict__ wq,
    const float* __restrict__ wk, const float* __restrict__ wv,
    const float* __restrict__ wo)
{
    int gf = blockIdx.x * 8 + (threadIdx.x >> 5);
    int lane = threadIdx.x & 31;
    int g = lane >> 2, qd = lane & 3;
    uint32_t hi[4], lo[4];
    size_t dst;
    if (gf < 49152) {  // A-type frags: 3 modes x 16384
        int mode = gf >> 14;
        int f = gf & 16383;
        int mt = f & 3, kt = (f >> 2) & 63, rt = f >> 8;
        const float* X = (mode == 0) ? q : (mode == 1) ? k : v;
        int row0 = rt * 64 + mt * 16 + g;
        int k0 = kt * 16 + qd * 2;
        const float* r0 = X + (size_t)row0 * D_MODEL + k0;
        const float* r8 = r0 + 8 * D_MODEL;
        hi[0] = pack_pair(r0[0], r0[1], lo[0]);
        hi[1] = pack_pair(r8[0], r8[1], lo[1]);
        hi[2] = pack_pair(r0[8], r0[9], lo[2]);
        hi[3] = pack_pair(r8[8], r8[9], lo[3]);
        dst = (size_t)mode * XELE + (size_t)f * 256 + lane * 8;
    } else {           // B-type frags: 4 weights x 4096
        int bf = gf - 49152;
        int w = bf >> 12;
        int f = bf & 4095;
        int nt8 = f >> 5, ktp = f & 31;
        const float* W = (w == 0) ? wq : (w == 1) ? wk : (w == 2) ? wv : wo;
        const float* r = W + (size_t)(nt8 * 8 + g) * D_MODEL + ktp * 32 + qd * 2;
        hi[0] = pack_pair(r[0], r[1], lo[0]);
        hi[1] = pack_pair(r[8], r[9], lo[1]);
        hi[2] = pack_pair(r[16], r[17], lo[2]);
        hi[3] = pack_pair(r[24], r[25], lo[3]);
        dst = 3 * (size_t)XELE + (size_t)w * WELE + (size_t)f * 256 + lane * 8;
    }
    *(uint4*)(g_BH + dst) = make_uint4(hi[0], hi[1], hi[2], hi[3]);
    *(uint4*)(g_BL + dst) = make_uint4(lo[0], lo[1], lo[2], lo[3]);
}

// ---------------------------------------------------------------------------
// Fragment GEMM (unchanged from R10/R12).
// ---------------------------------------------------------------------------
__global__ __launch_bounds__(256, 1) void gemm_frag(
    int mode, float* __restrict__ Yout,
    const float* __restrict__ b0p, const float* __restrict__ b1p,
    const float* __restrict__ b2p)
{
    int md = (mode < 0) ? (int)blockIdx.z : 3;
    const __nv_bfloat16 *AHp, *ALp;
    const float* bias;
    if (md < 3) {
        AHp = g_BH + (size_t)md * XELE;
        ALp = g_BL + (size_t)md * XELE;
        bias = (md == 0) ? b0p : (md == 1) ? b1p : b2p;
    } else {
        AHp = g_CH; ALp = g_CL; bias = b2p;
    }
    int wsel = (md == 3) ? 3 : md;
    const __nv_bfloat16* BHp = g_BH + 3 * (size_t)XELE + (size_t)wsel * WELE;
    const __nv_bfloat16* BLp = g_BL + 3 * (size_t)XELE + (size_t)wsel * WELE;

    int tid = threadIdx.x, lane = tid & 31, wid = tid >> 5;
    int warp_m = wid & 1, warp_n = wid >> 1;
    int m0 = blockIdx.y * 128, n0 = blockIdx.x * 128;
    int rt0 = (m0 >> 6) + warp_m;
    int nt80 = (n0 >> 3) + warp_n * 4;

    const uint4* aH = (const uint4*)AHp + (size_t)rt0 * 8192 + lane;
    const uint4* aL = (const uint4*)ALp + (size_t)rt0 * 8192 + lane;
    const uint4* bH = (const uint4*)BHp + (size_t)nt80 * 1024 + lane;
    const uint4* bL = (const uint4*)BLp + (size_t)nt80 * 1024 + lane;

    float acc[4][4][4];
#pragma unroll
    for (int i = 0; i < 4; ++i)
#pragma unroll
        for (int j = 0; j < 4; ++j)
#pragma unroll
            for (int c = 0; c < 4; ++c) acc[i][j][c] = 0.f;

    for (int ktp = 0; ktp < 32; ++ktp) {
        uint4 fah[4][2], fal[4][2], fbh[4], fbl[4];
#pragma unroll
        for (int mt = 0; mt < 4; ++mt)
#pragma unroll
            for (int kk = 0; kk < 2; ++kk) {
                int kt = ktp * 2 + kk;
                fah[mt][kk] = aH[(kt * 4 + mt) * 32];
                fal[mt][kk] = aL[(kt * 4 + mt) * 32];
            }
#pragma unroll
        for (int nb = 0; nb < 4; ++nb) {
            fbh[nb] = bH[(nb * 32 + ktp) * 32];
            fbl[nb] = bL[(nb * 32 + ktp) * 32];
        }
#pragma unroll
        for (int kk = 0; kk < 2; ++kk) {
#pragma unroll
            for (int mt = 0; mt < 4; ++mt) {
                uint32_t ah0 = fah[mt][kk].x, ah1 = fah[mt][kk].y,
                         ah2 = fah[mt][kk].z, ah3 = fah[mt][kk].w;
                uint32_t al0 = fal[mt][kk].x, al1 = fal[mt][kk].y,
                         al2 = fal[mt][kk].z, al3 = fal[mt][kk].w;
#pragma unroll
                for (int nb = 0; nb < 4; ++nb) {
                    uint32_t b0 = kk ? fbh[nb].z : fbh[nb].x;
                    uint32_t b1 = kk ? fbh[nb].w : fbh[nb].y;
                    uint32_t c0 = kk ? fbl[nb].z : fbl[nb].x;
                    uint32_t c1 = kk ? fbl[nb].w : fbl[nb].y;
                    MMA16816_V(acc[mt][nb], ah0, ah1, ah2, ah3, b0, b1);
                    MMA16816_V(acc[mt][nb], ah0, ah1, ah2, ah3, c0, c1);
                    MMA16816_V(acc[mt][nb], al0, al1, al2, al3, b0, b1);
                }
            }
        }
    }

    // ---- epilogue ----
    int g = lane >> 2, c2 = (lane & 3) * 2;
#pragma unroll
    for (int mt = 0; mt < 4; ++mt) {
#pragma unroll
        for (int nb = 0; nb < 4; ++nb) {
            int m = m0 + warp_m * 64 + mt * 16 + g;
            int n = n0 + warp_n * 32 + nb * 8 + c2;
            float2 bs = *(const float2*)&bias[n];
            float2 lo = make_float2(acc[mt][nb][0] + bs.x, acc[mt][nb][1] + bs.y);
            float2 hi = make_float2(acc[mt][nb][2] + bs.x, acc[mt][nb][3] + bs.y);
            if (md == 3) {
                *(float2*)&Yout[(size_t)m * D_MODEL + n] = lo;
                *(float2*)&Yout[(size_t)(m + 8) * D_MODEL + n] = hi;
            } else {
                __nv_bfloat16* DH = (md == 0) ? g_QH : (md == 1) ? g_KH : g_VH;
                __nv_bfloat16* DL = (md == 0) ? g_QL : (md == 1) ? g_KL : g_VL;
                int hh = n >> 6, dd = n & 63;
                int b2a = m >> 11, ssa = m & (S_LEN - 1);
                int b2b = (m + 8) >> 11, ssb = (m + 8) & (S_LEN - 1);
                size_t o1 = (((size_t)b2a * NH + hh) * S_LEN + ssa) * HD + dd;
                size_t o2 = (((size_t)b2b * NH + hh) * S_LEN + ssb) * HD + dd;
                uint32_t plo, phi;
                phi = pack_pair(lo.x, lo.y, plo);
                *(uint32_t*)&DH[o1] = phi;
                *(uint32_t*)&DL[o1] = plo;
                phi = pack_pair(hi.x, hi.y, plo);
                *(uint32_t*)&DH[o2] = phi;
                *(uint32_t*)&DL[o2] = plo;
            }
        }
    }
}

// ---------------------------------------------------------------------------
// Tensor-core attention; coalesced K/V loader; epilogue writes ctx A-frags.
// ---------------------------------------------------------------------------
#define OFF_QH 0
#define OFF_QL 4096
#define OFF_KH 8192
#define OFF_KL 24576
#define OFF_VH 40960
#define OFF_VL 57344
#define OFF_PH 73728
#define OFF_PL 81920
#define OFF_RS 90112
#define OFF_INV 90624
#define OFF_GS 90752
#define OFF_GV 90880
#define SMEM_ATTN 91008

__global__ __launch_bounds__(256, 2) void attn_mma(const int* __restrict__ gidx)
{
    extern __shared__ __align__(128) char sm[];
    const uint32_t smb = smem_u32(sm);
    float* rssm = (float*)(sm + OFF_RS);
    float* invsm = (float*)(sm + OFF_INV);
    int* gshs = (int*)(sm + OFF_GS);
    int* gvals = (int*)(sm + OFF_GV);

    int tid = threadIdx.x, lane = tid & 31, wid = tid >> 5;
    int warp_m = wid & 1, warp_n = wid >> 1;
    int b = blockIdx.z, h = blockIdx.y, bx = blockIdx.x;
    bool gt = (bx == 64);
    size_t hb = ((size_t)(b * NH + h)) * S_LEN * HD;

    if (tid < NG) { gshs[tid] = gidx[tid]; gvals[tid] = g_gvalid[tid]; }
    __syncthreads();

    int p = 0, rp0 = 0, i0 = 0, jps = 0, nloc = 0, ntile;
    if (gt) {
        ntile = 16;
    } else {
        p = bx & 1;
        int t2 = bx >> 1;
        rp0 = t2 * 32;
        i0 = t2 * 64 + p;
        jps = rp0 - 256; if (jps < 0) jps = 0;
        int jpe = rp0 + 287; if (jpe > 1023) jpe = 1023;
        nloc = (jpe - jps + 128) >> 7;
        ntile = nloc + 1;
    }

    // Q tile load (32 rows x 64 d, hi+lo)
    {
        int r = tid >> 3, uq = tid & 7;
        int irow = gt ? gshs[r] : (i0 + 2 * r);
        size_t go = hb + (size_t)irow * HD + uq * 8;
        uint32_t doff = (uint32_t)r * 128u + (uint32_t)((uq ^ (r & 7)) << 4);
        *(uint4*)(sm + OFF_QH + doff) = *(const uint4*)(g_QH + go);
        *(uint4*)(sm + OFF_QL + doff) = *(const uint4*)(g_QL + go);
    }

    int g = lane >> 2, c2 = (lane & 3) * 2;
    int r1 = warp_m * 16 + g, r2 = r1 + 8;
    int i1 = gt ? gshs[r1] : (i0 + 2 * r1);
    int i2 = gt ? gshs[r2] : (i0 + 2 * r2);
    int lsw = lane & 7;

    float rs1 = 0.f, rs2 = 0.f;
    float oacc[2][4];
#pragma unroll
    for (int i = 0; i < 2; ++i)
#pragma unroll
        for (int j = 0; j < 4; ++j) oacc[i][j] = 0.f;

    int uld = tid & 7, rowgrp = tid >> 3;  // coalesced loader mapping

    for (int ti = 0; ti < ntile; ++ti) {
        bool gcol = (!gt) && (ti == nloc);
        __syncthreads();  // previous tile fully consumed
        // ---- K/V tile load: 8 lanes cover one 128B row contiguously ----
#pragma unroll
        for (int it = 0; it < 4; ++it) {
            if (gcol && it > 0) continue;  // gcol: rows >=32 never read
            int slot = rowgrp + 32 * it;
            int s = 0;
            bool valid;
            if (gt) { s = (ti << 7) + slot; valid = true; }
            else if (ti < nloc) {
                int jp = jps + (ti << 7) + slot;
                valid = jp < 1024;
                s = 2 * jp + p;
            } else {
                valid = slot < 32;
                s = valid ? gshs[slot] : 0;
            }
            size_t ro = hb + (size_t)s * HD + uld * 8;
            uint32_t off = (uint32_t)slot * 128u +
                           (uint32_t)((uld ^ (slot & 7)) << 4);
            uint4 z = make_uint4(0, 0, 0, 0);
            *(uint4*)(sm + OFF_KH + off) = valid ? *(const uint4*)(g_KH + ro) : z;
            *(uint4*)(sm + OFF_KL + off) = valid ? *(const uint4*)(g_KL + ro) : z;
            *(uint4*)(sm + OFF_VH + off) = valid ? *(const uint4*)(g_VH + ro) : z;
            *(uint4*)(sm + OFF_VL + off) = valid ? *(const uint4*)(g_VL + ro) : z;
        }
        __syncthreads();

        // ---- S = Q*K^T (3-term split) ----
        float sacc[4][4];
#pragma unroll
        for (int i = 0; i < 4; ++i)
#pragma unroll
            for (int j = 0; j < 4; ++j) sacc[i][j] = 0.f;

        if (!(gcol && warp_n > 0)) {  // gcol: only warp_n==0 has live cols
#pragma unroll
            for (int ks = 0; ks < 4; ++ks) {
                uint32_t qhf[4], qlf[4];
                {
                    int rowA = warp_m * 16 + (lane & 15);
                    uint32_t addr = smb + OFF_QH + (uint32_t)rowA * 128u +
                                    (uint32_t)((((ks * 2 + (lane >> 4)) ^ lsw) & 7) << 4);
                    LDM4(qhf, addr);
                    LDM4(qlf, addr + (OFF_QL - OFF_QH));
                }
                uint32_t khf[2][4], klf[2][4];
#pragma unroll
                for (int nb = 0; nb < 2; ++nb) {
                    int rowB = warp_n * 32 + nb * 16 + ((lane >> 4) << 3) + lsw;
                    uint32_t addr = smb + OFF_KH + (uint32_t)rowB * 128u +
                                    (uint32_t)((((ks * 2 + ((lane >> 3) & 1)) ^ lsw) & 7) << 4);
                    LDM4(khf[nb], addr);
                    LDM4(klf[nb], addr + (OFF_KL - OFF_KH));
                }
#pragma unroll
                for (int nt = 0; nt < 4; ++nt) {
                    int nb = nt >> 1, hp = (nt & 1) * 2;
                    MMA16816(sacc[nt], qhf, khf[nb][hp], khf[nb][hp + 1]);
                    MMA16816(sacc[nt], qhf, klf[nb][hp], klf[nb][hp + 1]);
                    MMA16816(sacc[nt], qlf, khf[nb][hp], khf[nb][hp + 1]);
                }
            }
        }

        // ---- mask + exp + P split store ----
#pragma unroll
        for (int nt = 0; nt < 4; ++nt) {
            int c0 = warp_n * 32 + nt * 8 + c2;
            bool ok00, ok01, ok10, ok11;
            if (gt) {
                ok00 = ok01 = ok10 = ok11 = true;
            } else if (ti < nloc) {
                int jp0 = jps + (ti << 7) + c0;
                bool j0 = jp0 < 1024, j1 = (jp0 + 1) < 1024;
                int a0 = jp0 - (rp0 + r1);
                int b0_ = jp0 - (rp0 + r2);
                ok00 = j0 && a0 >= -256 && a0 <= 256;
                ok01 = j1 && (a0 + 1) >= -256 && (a0 + 1) <= 256;
                ok10 = j0 && b0_ >= -256 && b0_ <= 256;
                ok11 = j1 && (b0_ + 1) >= -256 && (b0_ + 1) <= 256;
            } else {
                ok00 = ok01 = ok10 = ok11 = false;
                if (c0 < 32) {
                    int s0 = gshs[c0];
                    bool gv = gvals[c0] != 0;
                    int d0 = s0 - i1;
                    ok00 = gv && !(((d0 & 1) == 0) && d0 >= -512 && d0 <= 512);
                    int d2 = s0 - i2;
                    ok10 = gv && !(((d2 & 1) == 0) && d2 >= -512 && d2 <= 512);
                }
                if (c0 + 1 < 32) {
                    int s1 = gshs[c0 + 1];
                    bool gv = gvals[c0 + 1] != 0;
                    int d1 = s1 - i1;
                    ok01 = gv && !(((d1 & 1) == 0) && d1 >= -512 && d1 <= 512);
                    int d3 = s1 - i2;
                    ok11 = gv && !(((d3 & 1) == 0) && d3 >= -512 && d3 <= 512);
                }
            }
            float p00 = ok00 ? __expf(sacc[nt][0] * 0.125f) : 0.f;
            float p01 = ok01 ? __expf(sacc[nt][1] * 0.125f) : 0.f;
            float p10 = ok10 ? __expf(sacc[nt][2] * 0.125f) : 0.f;
            float p11 = ok11 ? __expf(sacc[nt][3] * 0.125f) : 0.f;
            rs1 += p00 + p01;
            rs2 += p10 + p11;

            uint32_t un = (uint32_t)(c0 >> 3);
            uint32_t inb = (uint32_t)((c0 & 7) * 2);
            {
                uint32_t u1 = (un & 8u) | ((un ^ (uint32_t)(r1 & 7)) & 7u);
                uint32_t off = (uint32_t)r1 * 256u + (u1 << 4) + inb;
                uint32_t plo, phi;
                phi = pack_pair(p00, p01, plo);
                *(uint32_t*)(sm + OFF_PH + off) = phi;
                *(uint32_t*)(sm + OFF_PL + off) = plo;
            }
            {
                uint32_t u1 = (un & 8u) | ((un ^ (uint32_t)(r2 & 7)) & 7u);
                uint32_t off = (uint32_t)r2 * 256u + (u1 << 4) + inb;
                uint32_t plo, phi;
                phi = pack_pair(p10, p11, plo);
                *(uint32_t*)(sm + OFF_PH + off) = phi;
                *(uint32_t*)(sm + OFF_PL + off) = plo;
            }
        }
        __syncthreads();

        // ---- O += P * V (3-term split, V via ldmatrix.trans) ----
        int ksN = gcol ? 2 : 8;  // gcol tile: only j<32 contribute
        for (int ks = 0; ks < ksN; ++ks) {
            uint32_t phf[4], plf[4];
            {
                int rowP = warp_m * 16 + (lane & 15);
                uint32_t un = (uint32_t)(ks * 2 + (lane >> 4));
                uint32_t u1 = (un & 8u) | ((un ^ (uint32_t)(rowP & 7)) & 7u);
                uint32_t addr = smb + OFF_PH + (uint32_t)rowP * 256u + (u1 << 4);
                LDM4(phf, addr);
                LDM4(plf, addr + (OFF_PL - OFF_PH));
            }
            uint32_t vhf[4], vlf[4];
            {
                int rowV = ks * 16 + (lane & 15);
                uint32_t un = (uint32_t)((warp_n * 2 + (lane >> 4)) ^ (rowV & 7));
                uint32_t addr = smb + OFF_VH + (uint32_t)rowV * 128u + (un << 4);
                LDM4T(vhf, addr);
                LDM4T(vlf, addr + (OFF_VL - OFF_VH));
            }
#pragma unroll
            for (int nt2 = 0; nt2 < 2; ++nt2) {
                int hp = nt2 * 2;
                MMA16816(oacc[nt2], phf, vhf[hp], vhf[hp + 1]);
                MMA16816(oacc[nt2], phf, vlf[hp], vlf[hp + 1]);
                MMA16816(oacc[nt2], plf, vhf[hp], vhf[hp + 1]);
            }
        }
    }

    // ---- rsum reduction ----
    rs1 += __shfl_xor_sync(0xffffffffu, rs1, 1);
    rs1 += __shfl_xor_sync(0xffffffffu, rs1, 2);
    rs2 += __shfl_xor_sync(0xffffffffu, rs2, 1);
    rs2 += __shfl_xor_sync(0xffffffffu, rs2, 2);
    if ((lane & 3) == 0) {
        rssm[warp_n * 32 + r1] = rs1;
        rssm[warp_n * 32 + r2] = rs2;
    }
    __syncthreads();
    if (tid < 32) {
        float t = rssm[tid] + rssm[32 + tid] + rssm[64 + tid] + rssm[96 + tid];
        invsm[tid] = 1.f / t;
    }
    __syncthreads();

    // ---- epilogue: write ctx A-fragments (hi/lo) directly ----
    float inv1 = invsm[r1], inv2 = invsm[r2];
    bool w1 = gt || (g_isg[i1] == 0);
    bool w2 = gt || (g_isg[i2] == 0);
    int m1 = b * S_LEN + i1, m2 = b * S_LEN + i2;
#pragma unroll
    for (int nt2 = 0; nt2 < 2; ++nt2) {
        int d = warp_n * 16 + nt2 * 8 + c2;
        int n = h * HD + d;
        int kt = n >> 4;
        int qd = (n >> 1) & 3;
        int half8 = (n >> 3) & 1;
        if (w1) {
            uint32_t plo, phi;
            phi = pack_pair(oacc[nt2][0] * inv1, oacc[nt2][1] * inv1, plo);
            int rt = m1 >> 6, mt = (m1 >> 4) & 3, r16 = m1 & 15;
            int lane_p = (r16 & 7) * 4 + qd;
            int reg = (r16 >> 3) + 2 * half8;
            size_t dst = ((size_t)(rt * 64 + kt) * 4 + mt) * 256 + lane_p * 8 + reg * 2;
            *(uint32_t*)(g_CH + dst) = phi;
            *(uint32_t*)(g_CL + dst) = plo;
        }
        if (w2) {
            uint32_t plo, phi;
            phi = pack_pair(oacc[nt2][2] * inv2, oacc[nt2][3] * inv2, plo);
            int rt = m2 >> 6, mt = (m2 >> 4) & 3, r16 = m2 & 15;
            int lane_p = (r16 & 7) * 4 + qd;
            int reg = (r16 >> 3) + 2 * half8;
            size_t dst = ((size_t)(rt * 64 + kt) * 4 + mt) * 256 + lane_p * 8 + reg * 2;
            *(uint32_t*)(g_CH + dst) = phi;
            *(uint32_t*)(g_CL + dst) = plo;
        }
    }
}

// ---------------------------------------------------------------------------
extern "C" void kernel_launch(void* const* d_in, const int* in_sizes, int n_in,
                              void* d_out, int out_size) {
    const float* q  = (const float*)d_in[0];
    const float* k  = (const float*)d_in[1];
    const float* v  = (const float*)d_in[2];
    const float* Wq = (const float*)d_in[3];
    const float* Wk = (const float*)d_in[4];
    const float* Wv = (const float*)d_in[5];
    const float* Wo = (const float*)d_in[6];
    const float* bq = (const float*)d_in[7];
    const float* bk = (const float*)d_in[8];
    const float* bv = (const float*)d_in[9];
    const float* bo = (const float*)d_in[10];
    const int* gidx = (const int*)d_in[11];
    float* out = (float*)d_out;

    cudaFuncSetAttribute(attn_mma, cudaFuncAttributeMaxDynamicSharedMemorySize,
                         SMEM_ATTN);

    flags_kernel<<<1, 256>>>(gidx);
    pack_all<<<8192, 256>>>(q, k, v, Wq, Wk, Wv, Wo);

    // Fused QKV projection (grid z selects Q/K/V); writes bf16 hi/lo splits.
    gemm_frag<<<dim3(D_MODEL / 128, SN / 128, 3), 256>>>(-1, nullptr, bq, bk, bv);

    // Attention writes ctx A-fragments directly (no fp32 ctx / pack pass).
    attn_mma<<<dim3(65, NH, NB), 256, SMEM_ATTN>>>(gidx);

    gemm_frag<<<dim3(D_MODEL / 128, SN / 128, 1), 256>>>(3, out, bo, bo, bo);
}